// round 3
// baseline (speedup 1.0000x reference)
#include <cuda_runtime.h>

// ---------------- problem constants ----------------
constexpr int B_   = 64;
constexpr int T_   = 12;
constexpr int N_   = 325;
constexpr int H_   = 64;
constexpr int E_   = 32;
constexpr int LH_  = 128;
constexpr int OUT_ = 12;
constexpr int C_   = 97;   // 1 + 64 + 32 channels
constexpr int MOFF = 65;

constexpr int ROWS = 32;                         // n-rows per block
constexpr int NBLK = (N_ + ROWS - 1) / ROWS;     // 11
constexpr int THR  = 256;                        // 64 j x 4 row-groups of 8

// ---------------- scratch (device globals) ----------------
__device__ float  g_hid[3 * 4 * B_ * LH_];       // stage-1 hidden activations
// Wh packed: g_WhA[b][ip*64+j] = {W0[2ip][j],W0[2ip+1][j],W1[2ip][j],W1[2ip+1][j]}
__device__ float4 g_WhA[B_][32 * 64];
__device__ float4 g_WhB[B_][32 * 64];
__device__ float  g_Wx[B_ * H_ * 4];             // [b][j][g]
__device__ float  g_Bb[B_ * H_ * 4];             // [b][j][g]

// ---------------- helpers ----------------
__device__ __forceinline__ unsigned long long pack2(float lo, float hi) {
    unsigned long long r;
    asm("mov.b64 %0, {%1,%2};" : "=l"(r) : "f"(lo), "f"(hi));
    return r;
}
__device__ __forceinline__ float hadd2(unsigned long long v) {
    float lo, hi;
    asm("mov.b64 {%0,%1}, %2;" : "=f"(lo), "=f"(hi) : "l"(v));
    return lo + hi;
}
__device__ __forceinline__ void fma2(unsigned long long& d,
                                     unsigned long long a,
                                     unsigned long long b) {
    asm("fma.rn.f32x2 %0, %1, %2, %0;" : "+l"(d) : "l"(a), "l"(b));
}
__device__ __forceinline__ float ex2a(float x) {
    float r; asm("ex2.approx.f32 %0, %1;" : "=f"(r) : "f"(x)); return r;
}
__device__ __forceinline__ float rcpa(float x) {
    float r; asm("rcp.approx.f32 %0, %1;" : "=f"(r) : "f"(x)); return r;
}
__device__ __forceinline__ float sig_a(float x) {
    return rcpa(1.0f + ex2a(-1.4426950408889634f * x));
}
__device__ __forceinline__ float tanh_a(float x) {
    float e = ex2a(2.8853900817779268f * x);
    return fmaf(-2.0f, rcpa(e + 1.0f), 1.0f);
}

// ============ stage 1: meta + first MLP layer ============
// grid = 12 blocks (m in 0..2, g in 0..3); W1 tile staged once per block.
__global__ void stage1_kernel(const float* __restrict__ x,
                              const float* __restrict__ wxW1, const float* __restrict__ wxB1,
                              const float* __restrict__ whW1, const float* __restrict__ whB1,
                              const float* __restrict__ lbW1, const float* __restrict__ lbB1) {
    int m = blockIdx.x >> 2, g = blockIdx.x & 3;
    const float* W1 = (m == 0) ? wxW1 : (m == 1) ? whW1 : lbW1;
    const float* b1 = (m == 0) ? wxB1 : (m == 1) ? whB1 : lbB1;
    __shared__ float meta[B_][E_];     // 8 KB
    __shared__ float w1s[E_ * LH_];    // 16 KB
    int tid = threadIdx.x;

    // meta[b][e] = mean over t (each block recomputes; L2-cached after first)
#pragma unroll
    for (int i = 0; i < 8; i++) {
        int idx = tid + i * THR;           // 2048 total
        int b = idx >> 5, e = idx & 31;
        float s = 0.f;
#pragma unroll
        for (int t = 0; t < T_; t++)
            s += x[(size_t)((b * T_ + t) * N_) * C_ + MOFF + e];
        meta[b][e] = s * (1.0f / 12.0f);
    }
    const float* W1g = W1 + g * E_ * LH_;
    for (int i = tid; i < E_ * LH_; i += THR) w1s[i] = W1g[i];
    __syncthreads();

#pragma unroll
    for (int i = 0; i < 32; i++) {
        int idx = tid + i * THR;           // 8192 outputs
        int b = idx >> 7, l = idx & 127;
        float acc = b1[g * LH_ + l];
#pragma unroll
        for (int e = 0; e < E_; e++)
            acc = fmaf(meta[b][e], w1s[e * LH_ + l], acc);
        g_hid[((m * 4 + g) * B_ + b) * LH_ + l] = fmaxf(acc, 0.f);
    }
}

// ============ stage 2: second MLP layer as batched GEMM ============
__global__ void stage2_kernel(const float* __restrict__ wxW2, const float* __restrict__ wxB2,
                              const float* __restrict__ whW2, const float* __restrict__ whB2,
                              const float* __restrict__ lbW2, const float* __restrict__ lbB2) {
    __shared__ float hs[B_ * LH_];    // 32KB
    __shared__ float w2[LH_ * 64];    // 32KB
    int g  = blockIdx.x / 66;
    int tl = blockIdx.x % 66;
    int m  = (tl < 64) ? 1 : (tl == 64 ? 0 : 2);
    int tile = (m == 1) ? tl : 0;
    int tid = threadIdx.x;
    int o = tid & 63, bg = tid >> 6;

    const float* hsrc = g_hid + (m * 4 + g) * (B_ * LH_);
    for (int i = tid; i < B_ * LH_; i += 256) hs[i] = hsrc[i];
    const float* W2; const float* b2; int ostride;
    if (m == 1)      { W2 = whW2 + g * LH_ * 4096 + tile * 64; b2 = whB2 + g * 4096 + tile * 64; ostride = 4096; }
    else if (m == 0) { W2 = wxW2 + g * LH_ * 64;               b2 = wxB2 + g * 64;               ostride = 64; }
    else             { W2 = lbW2 + g * LH_ * 64;               b2 = lbB2 + g * 64;               ostride = 64; }
    for (int i = tid; i < LH_ * 64; i += 256) {
        int k = i >> 6, oo = i & 63;
        w2[i] = W2[k * ostride + oo];
    }
    __syncthreads();

    float bv = b2[o];
    float acc[16];
#pragma unroll
    for (int i = 0; i < 16; i++) acc[i] = bv;
    const float* hb = hs + bg * 16 * LH_;
#pragma unroll 4
    for (int k = 0; k < LH_; k++) {
        float w = w2[k * 64 + o];
#pragma unroll
        for (int i = 0; i < 16; i++)
            acc[i] = fmaf(hb[i * LH_ + k], w, acc[i]);
    }

#pragma unroll
    for (int i = 0; i < 16; i++) {
        int b = bg * 16 + i;
        if (m == 0)      g_Wx[(b * H_ + o) * 4 + g] = acc[i];
        else if (m == 2) g_Bb[(b * H_ + o) * 4 + g] = acc[i];
        else {
            float* base = (g < 2) ? (float*)g_WhA[b] : (float*)g_WhB[b];
            base[(((tile >> 1) * 64) + o) * 4 + ((g & 1) << 1) + (tile & 1)] = acc[i];
        }
    }
}

// ============ stage 3: LSTM recurrence + output head ============
struct SMEM {
    float4 WA[32 * 64];        // 32 KB  gates 0,1
    float4 WB[32 * 64];        // 32 KB  gates 2,3
    float  h[2][ROWS][H_];     // 16 KB  double-buffered
    float  xs[ROWS][T_];       // 1.5 KB
    float4 wx[H_];             // 1 KB
    float4 bi[H_];             // 1 KB
};

__global__ void __launch_bounds__(THR, 2)
lstm_kernel(const float* __restrict__ x,
            const float* __restrict__ fc1W, const float* __restrict__ fc1b,
            const float* __restrict__ fc2W, const float* __restrict__ fc2b,
            float* __restrict__ out) {
    extern __shared__ char smraw[];
    SMEM* s = (SMEM*)smraw;
    int b  = blockIdx.y;
    int n0 = blockIdx.x * ROWS;
    int tid = threadIdx.x;

    const float4* srcA = g_WhA[b];
    const float4* srcB = g_WhB[b];
    for (int i = tid; i < 32 * 64; i += THR) { s->WA[i] = srcA[i]; s->WB[i] = srcB[i]; }
    for (int i = tid; i < ROWS * T_; i += THR) {
        int r = i / T_, t = i - r * T_;
        int n = n0 + r;
        s->xs[r][t] = (n < N_) ? x[(size_t)((b * T_ + t) * N_ + n) * C_] : 0.f;
    }
    for (int i = tid; i < ROWS * H_; i += THR) ((float*)s->h[0])[i] = 0.f;
    if (tid < H_) {
        s->wx[tid] = *(const float4*)&g_Wx[(b * H_ + tid) * 4];
        s->bi[tid] = *(const float4*)&g_Bb[(b * H_ + tid) * 4];
    }
    __syncthreads();

    int w = tid >> 5, lane = tid & 31;
    int j  = ((w & 1) << 5) | lane;   // output index 0..63
    int r0 = (w >> 1) * 8;            // row-group base (8 rows, 4 groups)

    float4 wx4 = s->wx[j];
    float4 bi4 = s->bi[j];

    float c[8];
#pragma unroll
    for (int r = 0; r < 8; r++) c[r] = 0.f;

    int p = 0;
    for (int t = 0; t < T_; t++) {
        unsigned long long z0[8], z1[8], z2[8], z3[8];
#pragma unroll
        for (int r = 0; r < 8; r++) {
            float xv = s->xs[r0 + r][t];
            z0[r] = pack2(fmaf(xv, wx4.x, bi4.x), 0.f);
            z1[r] = pack2(fmaf(xv, wx4.y, bi4.y), 0.f);
            z2[r] = pack2(fmaf(xv, wx4.z, bi4.z), 0.f);
            z3[r] = pack2(fmaf(xv, wx4.w, bi4.w), 0.f);
        }
        const float* hbase = &s->h[p][0][0];
        // k-quad loop: q covers k = 4q..4q+3 (ips 2q and 2q+1)
#pragma unroll 4
        for (int q = 0; q < 16; q++) {
            ulonglong2 a0 = *(const ulonglong2*)&s->WA[(2 * q)     * 64 + j];
            ulonglong2 a1 = *(const ulonglong2*)&s->WA[(2 * q + 1) * 64 + j];
            ulonglong2 b0 = *(const ulonglong2*)&s->WB[(2 * q)     * 64 + j];
            ulonglong2 b1 = *(const ulonglong2*)&s->WB[(2 * q + 1) * 64 + j];
#pragma unroll
            for (int r = 0; r < 8; r++) {
                ulonglong2 h2 = *(const ulonglong2*)&hbase[(r0 + r) * H_ + 4 * q];
                fma2(z0[r], a0.x, h2.x);
                fma2(z0[r], a1.x, h2.y);
                fma2(z1[r], a0.y, h2.x);
                fma2(z1[r], a1.y, h2.y);
                fma2(z2[r], b0.x, h2.x);
                fma2(z2[r], b1.x, h2.y);
                fma2(z3[r], b0.y, h2.x);
                fma2(z3[r], b1.y, h2.y);
            }
        }
#pragma unroll
        for (int r = 0; r < 8; r++) {
            float gg = tanh_a(hadd2(z0[r]));
            float ii = sig_a(hadd2(z1[r]));
            float ff = sig_a(hadd2(z2[r]));
            float oo = sig_a(hadd2(z3[r]));
            float cc = fmaf(gg, ii, c[r] * ff);
            c[r] = cc;
            s->h[p ^ 1][r0 + r][j] = tanh_a(cc) * oo;
        }
        __syncthreads();
        p ^= 1;
    }

    // ---- output head: relu(h) @ fc1 -> relu -> @ fc2 ----
#pragma unroll
    for (int q = 0; q < 4; q++) {
        int row = w + 8 * q;
        int n = n0 + row;
        float acc = fc1b[lane];
#pragma unroll 16
        for (int i = 0; i < 64; i++) {
            float hv = fmaxf(s->h[p][row][i], 0.f);
            acc = fmaf(hv, fc1W[i * 32 + lane], acc);
        }
        float o1 = fmaxf(acc, 0.f);
        float acc2 = (lane < OUT_) ? fc2b[lane] : 0.f;
#pragma unroll
        for (int jj = 0; jj < 32; jj++) {
            float v  = __shfl_sync(0xffffffffu, o1, jj);
            float wv = (lane < OUT_) ? fc2W[jj * OUT_ + lane] : 0.f;
            acc2 = fmaf(v, wv, acc2);
        }
        if (lane < OUT_ && n < N_)
            out[(size_t)(b * OUT_ + lane) * N_ + n] = acc2;
    }
}

// ---------------- launcher ----------------
extern "C" void kernel_launch(void* const* d_in, const int* in_sizes, int n_in,
                              void* d_out, int out_size) {
    const float* x      = (const float*)d_in[0];
    const float* lwx_W1 = (const float*)d_in[1];
    const float* lwx_b1 = (const float*)d_in[2];
    const float* lwx_W2 = (const float*)d_in[3];
    const float* lwx_b2 = (const float*)d_in[4];
    const float* lwh_W1 = (const float*)d_in[5];
    const float* lwh_b1 = (const float*)d_in[6];
    const float* lwh_W2 = (const float*)d_in[7];
    const float* lwh_b2 = (const float*)d_in[8];
    const float* lb_W1  = (const float*)d_in[9];
    const float* lb_b1  = (const float*)d_in[10];
    const float* lb_W2  = (const float*)d_in[11];
    const float* lb_b2  = (const float*)d_in[12];
    const float* fc1W   = (const float*)d_in[13];
    const float* fc1b   = (const float*)d_in[14];
    const float* fc2W   = (const float*)d_in[15];
    const float* fc2b   = (const float*)d_in[16];

    cudaFuncSetAttribute(lstm_kernel,
                         cudaFuncAttributeMaxDynamicSharedMemorySize,
                         (int)sizeof(SMEM));

    stage1_kernel<<<12, THR>>>(x, lwx_W1, lwx_b1, lwh_W1, lwh_b1, lb_W1, lb_b1);
    stage2_kernel<<<4 * 66, 256>>>(lwx_W2, lwx_b2, lwh_W2, lwh_b2, lb_W2, lb_b2);

    dim3 grid(NBLK, B_);
    lstm_kernel<<<grid, THR, sizeof(SMEM)>>>(x, fc1W, fc1b, fc2W, fc2b,
                                             (float*)d_out);
}

// round 8
// speedup vs baseline: 1.3812x; 1.3812x over previous
#include <cuda_runtime.h>

// ---------------- problem constants ----------------
constexpr int B_   = 64;
constexpr int T_   = 12;
constexpr int N_   = 325;
constexpr int H_   = 64;
constexpr int E_   = 32;
constexpr int LH_  = 128;
constexpr int OUT_ = 12;
constexpr int C_   = 97;   // 1 + 64 + 32 channels
constexpr int MOFF = 65;

constexpr int ROWS = 40;                         // n-rows per block
constexpr int NBLK = (N_ + ROWS - 1) / ROWS;     // 9 -> grid 576 = 1.95 waves
constexpr int THR  = 320;                        // 64 j x 5 row-groups of 8

// ---------------- scratch (device globals) ----------------
// Wh packed: g_WhA[b][ip*64+j] = {W0[2ip][j],W0[2ip+1][j],W1[2ip][j],W1[2ip+1][j]}
__device__ float4 g_WhA[B_][32 * 64];
__device__ float4 g_WhB[B_][32 * 64];
__device__ float  g_Wx[B_ * H_ * 4];             // [b][j][g]
__device__ float  g_Bb[B_ * H_ * 4];             // [b][j][g]

// ---------------- helpers ----------------
__device__ __forceinline__ unsigned long long pack2(float lo, float hi) {
    unsigned long long r;
    asm("mov.b64 %0, {%1,%2};" : "=l"(r) : "f"(lo), "f"(hi));
    return r;
}
__device__ __forceinline__ float hadd2(unsigned long long v) {
    float lo, hi;
    asm("mov.b64 {%0,%1}, %2;" : "=f"(lo), "=f"(hi) : "l"(v));
    return lo + hi;
}
__device__ __forceinline__ void fma2(unsigned long long& d,
                                     unsigned long long a,
                                     unsigned long long b) {
    asm("fma.rn.f32x2 %0, %1, %2, %0;" : "+l"(d) : "l"(a), "l"(b));
}
__device__ __forceinline__ float ex2a(float x) {
    float r; asm("ex2.approx.f32 %0, %1;" : "=f"(r) : "f"(x)); return r;
}
__device__ __forceinline__ float rcpa(float x) {
    float r; asm("rcp.approx.f32 %0, %1;" : "=f"(r) : "f"(x)); return r;
}
__device__ __forceinline__ float sig_a(float x) {
    return rcpa(1.0f + ex2a(-1.4426950408889634f * x));
}
__device__ __forceinline__ float tanh_a(float x) {
    float e = ex2a(2.8853900817779268f * x);
    return fmaf(-2.0f, rcpa(e + 1.0f), 1.0f);
}

// ============ prep: meta + both MLP layers, one block per (gate, out-tile) ============
// grid = 4 gates * 66 tiles (64 Wh o-tiles + 1 Wx + 1 bias), 256 threads.
// Each block recomputes meta (cheap, L2-hit) and layer-1 for its gate (262K FMA),
// then does the layer-2 GEMM tile. smem: meta 8KB + buf 32KB + hs 32KB = 72KB.
struct PrepSM {
    float meta[B_ * E_];     // 8 KB
    float hs[B_ * LH_];      // 32 KB
    float buf[LH_ * 64];     // 32 KB (holds W1 first, then W2 tile)
};

__global__ void prep_kernel(const float* __restrict__ x,
                            const float* __restrict__ wxW1, const float* __restrict__ wxB1,
                            const float* __restrict__ wxW2, const float* __restrict__ wxB2,
                            const float* __restrict__ whW1, const float* __restrict__ whB1,
                            const float* __restrict__ whW2, const float* __restrict__ whB2,
                            const float* __restrict__ lbW1, const float* __restrict__ lbB1,
                            const float* __restrict__ lbW2, const float* __restrict__ lbB2) {
    extern __shared__ char praw[];
    PrepSM* s = (PrepSM*)praw;
    int g  = blockIdx.x / 66;
    int tl = blockIdx.x % 66;
    int m  = (tl < 64) ? 1 : (tl == 64 ? 0 : 2);
    int tile = (m == 1) ? tl : 0;
    int tid = threadIdx.x;

    const float* W1; const float* b1; const float* W2; const float* b2; int ostride;
    if (m == 1)      { W1 = whW1; b1 = whB1; W2 = whW2 + g * LH_ * 4096 + tile * 64; b2 = whB2 + g * 4096 + tile * 64; ostride = 4096; }
    else if (m == 0) { W1 = wxW1; b1 = wxB1; W2 = wxW2 + g * LH_ * 64;               b2 = wxB2 + g * 64;               ostride = 64; }
    else             { W1 = lbW1; b1 = lbB1; W2 = lbW2 + g * LH_ * 64;               b2 = lbB2 + g * 64;               ostride = 64; }

    // phase 0: meta + stage W1[g] into buf
#pragma unroll
    for (int i = 0; i < 8; i++) {
        int idx = tid + i * 256;            // 2048 = 64 b x 32 e
        int b = idx >> 5, e = idx & 31;
        float sum = 0.f;
#pragma unroll
        for (int t = 0; t < T_; t++)
            sum += x[(size_t)((b * T_ + t) * N_) * C_ + MOFF + e];
        s->meta[idx] = sum * (1.0f / 12.0f);
    }
    const float* W1g = W1 + g * E_ * LH_;
    for (int i = tid; i < E_ * LH_; i += 256) s->buf[i] = W1g[i];
    __syncthreads();

    // phase 1: hs[b][l] = relu(b1 + meta[b] @ W1[g][:,l])
#pragma unroll
    for (int i = 0; i < 32; i++) {
        int idx = tid + i * 256;            // 8192 = 64 b x 128 l
        int b = idx >> 7, l = idx & 127;
        float acc = b1[g * LH_ + l];
#pragma unroll
        for (int e = 0; e < E_; e++)
            acc = fmaf(s->meta[b * E_ + e], s->buf[e * LH_ + l], acc);
        s->hs[idx] = fmaxf(acc, 0.f);
    }
    __syncthreads();

    // phase 2: stage W2 tile into buf (overwrites W1)
    for (int i = tid; i < LH_ * 64; i += 256) {
        int k = i >> 6, oo = i & 63;
        s->buf[i] = W2[k * ostride + oo];
    }
    __syncthreads();

    // phase 3: GEMM  (o = tid&63, 16 batches per thread)
    int o = tid & 63, bg = tid >> 6;
    float bv = b2[o];
    float acc[16];
#pragma unroll
    for (int i = 0; i < 16; i++) acc[i] = bv;
    const float* hb = s->hs + bg * 16 * LH_;
#pragma unroll 4
    for (int k = 0; k < LH_; k++) {
        float w = s->buf[k * 64 + o];
#pragma unroll
        for (int i = 0; i < 16; i++)
            acc[i] = fmaf(hb[i * LH_ + k], w, acc[i]);
    }

#pragma unroll
    for (int i = 0; i < 16; i++) {
        int b = bg * 16 + i;
        if (m == 0)      g_Wx[(b * H_ + o) * 4 + g] = acc[i];
        else if (m == 2) g_Bb[(b * H_ + o) * 4 + g] = acc[i];
        else {
            float* base = (g < 2) ? (float*)g_WhA[b] : (float*)g_WhB[b];
            base[(((tile >> 1) * 64) + o) * 4 + ((g & 1) << 1) + (tile & 1)] = acc[i];
        }
    }
}

// ============ LSTM recurrence + output head (exact round-2 version, 320us) ============
struct SMEM {
    float4 WA[32 * 64];        // 32 KB  gates 0,1
    float4 WB[32 * 64];        // 32 KB  gates 2,3
    float  h[2][ROWS][H_];     // 20 KB  double-buffered
    float  xs[ROWS][T_];       // 1.875 KB
    float4 wx[H_];             // 1 KB
    float4 bi[H_];             // 1 KB
};

__global__ void __launch_bounds__(THR, 2)
lstm_kernel(const float* __restrict__ x,
            const float* __restrict__ fc1W, const float* __restrict__ fc1b,
            const float* __restrict__ fc2W, const float* __restrict__ fc2b,
            float* __restrict__ out) {
    extern __shared__ char smraw[];
    SMEM* s = (SMEM*)smraw;
    int b  = blockIdx.y;
    int n0 = blockIdx.x * ROWS;
    int tid = threadIdx.x;

    const float4* srcA = g_WhA[b];
    const float4* srcB = g_WhB[b];
    for (int i = tid; i < 32 * 64; i += THR) { s->WA[i] = srcA[i]; s->WB[i] = srcB[i]; }
    for (int i = tid; i < ROWS * T_; i += THR) {
        int r = i / T_, t = i - r * T_;
        int n = n0 + r;
        s->xs[r][t] = (n < N_) ? x[(size_t)((b * T_ + t) * N_ + n) * C_] : 0.f;
    }
    for (int i = tid; i < ROWS * H_; i += THR) ((float*)s->h[0])[i] = 0.f;
    if (tid < H_) {
        s->wx[tid] = *(const float4*)&g_Wx[(b * H_ + tid) * 4];
        s->bi[tid] = *(const float4*)&g_Bb[(b * H_ + tid) * 4];
    }
    __syncthreads();

    int w = tid >> 5, lane = tid & 31;
    int j  = ((w & 1) << 5) | lane;   // output index 0..63
    int r0 = (w >> 1) * 8;            // row-group base (8 rows)

    float c[8];
#pragma unroll
    for (int r = 0; r < 8; r++) c[r] = 0.f;

    int p = 0;
    for (int t = 0; t < T_; t++) {
        float4 wx4 = s->wx[j];
        float4 bi4 = s->bi[j];
        unsigned long long z0[8], z1[8], z2[8], z3[8];
#pragma unroll
        for (int r = 0; r < 8; r++) {
            float xv = s->xs[r0 + r][t];
            z0[r] = pack2(fmaf(xv, wx4.x, bi4.x), 0.f);
            z1[r] = pack2(fmaf(xv, wx4.y, bi4.y), 0.f);
            z2[r] = pack2(fmaf(xv, wx4.z, bi4.z), 0.f);
            z3[r] = pack2(fmaf(xv, wx4.w, bi4.w), 0.f);
        }
        const float* hbase = &s->h[p][0][0];
#pragma unroll 8
        for (int ip = 0; ip < 32; ip++) {
            ulonglong2 a  = *(const ulonglong2*)&s->WA[ip * 64 + j];
            ulonglong2 bb = *(const ulonglong2*)&s->WB[ip * 64 + j];
#pragma unroll
            for (int r = 0; r < 8; r++) {
                unsigned long long hp =
                    *(const unsigned long long*)&hbase[(r0 + r) * H_ + 2 * ip];
                fma2(z0[r], a.x,  hp);
                fma2(z1[r], a.y,  hp);
                fma2(z2[r], bb.x, hp);
                fma2(z3[r], bb.y, hp);
            }
        }
#pragma unroll
        for (int r = 0; r < 8; r++) {
            float gg = tanh_a(hadd2(z0[r]));
            float ii = sig_a(hadd2(z1[r]));
            float ff = sig_a(hadd2(z2[r]));
            float oo = sig_a(hadd2(z3[r]));
            float cc = fmaf(gg, ii, c[r] * ff);
            c[r] = cc;
            s->h[p ^ 1][r0 + r][j] = tanh_a(cc) * oo;
        }
        __syncthreads();
        p ^= 1;
    }

    // ---- output head: relu(h) @ fc1 -> relu -> @ fc2 ----
#pragma unroll
    for (int q = 0; q < 4; q++) {
        int row = w + 10 * q;
        int n = n0 + row;
        float acc = fc1b[lane];
#pragma unroll 16
        for (int i = 0; i < 64; i++) {
            float hv = fmaxf(s->h[p][row][i], 0.f);
            acc = fmaf(hv, fc1W[i * 32 + lane], acc);
        }
        float o1 = fmaxf(acc, 0.f);
        float acc2 = (lane < OUT_) ? fc2b[lane] : 0.f;
#pragma unroll
        for (int jj = 0; jj < 32; jj++) {
            float v  = __shfl_sync(0xffffffffu, o1, jj);
            float wv = (lane < OUT_) ? fc2W[jj * OUT_ + lane] : 0.f;
            acc2 = fmaf(v, wv, acc2);
        }
        if (lane < OUT_ && n < N_)
            out[(size_t)(b * OUT_ + lane) * N_ + n] = acc2;
    }
}

// ---------------- launcher ----------------
extern "C" void kernel_launch(void* const* d_in, const int* in_sizes, int n_in,
                              void* d_out, int out_size) {
    const float* x      = (const float*)d_in[0];
    const float* lwx_W1 = (const float*)d_in[1];
    const float* lwx_b1 = (const float*)d_in[2];
    const float* lwx_W2 = (const float*)d_in[3];
    const float* lwx_b2 = (const float*)d_in[4];
    const float* lwh_W1 = (const float*)d_in[5];
    const float* lwh_b1 = (const float*)d_in[6];
    const float* lwh_W2 = (const float*)d_in[7];
    const float* lwh_b2 = (const float*)d_in[8];
    const float* lb_W1  = (const float*)d_in[9];
    const float* lb_b1  = (const float*)d_in[10];
    const float* lb_W2  = (const float*)d_in[11];
    const float* lb_b2  = (const float*)d_in[12];
    const float* fc1W   = (const float*)d_in[13];
    const float* fc1b   = (const float*)d_in[14];
    const float* fc2W   = (const float*)d_in[15];
    const float* fc2b   = (const float*)d_in[16];

    cudaFuncSetAttribute(prep_kernel,
                         cudaFuncAttributeMaxDynamicSharedMemorySize,
                         (int)sizeof(PrepSM));
    cudaFuncSetAttribute(lstm_kernel,
                         cudaFuncAttributeMaxDynamicSharedMemorySize,
                         (int)sizeof(SMEM));

    prep_kernel<<<4 * 66, 256, sizeof(PrepSM)>>>(
        x, lwx_W1, lwx_b1, lwx_W2, lwx_b2,
           lwh_W1, lwh_b1, lwh_W2, lwh_b2,
           lb_W1,  lb_b1,  lb_W2,  lb_b2);

    dim3 grid(NBLK, B_);
    lstm_kernel<<<grid, THR, sizeof(SMEM)>>>(x, fc1W, fc1b, fc2W, fc2b,
                                             (float*)d_out);
}

// round 9
// speedup vs baseline: 1.4004x; 1.0139x over previous
#include <cuda_runtime.h>

// ---------------- problem constants ----------------
constexpr int B_   = 64;
constexpr int T_   = 12;
constexpr int N_   = 325;
constexpr int H_   = 64;
constexpr int E_   = 32;
constexpr int LH_  = 128;
constexpr int OUT_ = 12;
constexpr int C_   = 97;   // 1 + 64 + 32 channels
constexpr int MOFF = 65;

constexpr int ROWS = 40;                         // n-rows per block
constexpr int NBLK = (N_ + ROWS - 1) / ROWS;     // 9 -> grid 576 = 1.95 waves
constexpr int THR  = 320;                        // 64 j x 5 row-groups of 8

// ---------------- scratch (device globals) ----------------
// Wh packed: g_WhA[b][ip*64+j] = {W0[2ip][j],W0[2ip+1][j],W1[2ip][j],W1[2ip+1][j]}
__device__ float4 g_WhA[B_][32 * 64];
__device__ float4 g_WhB[B_][32 * 64];
__device__ float  g_Wx[B_ * H_ * 4];             // [b][j][g]
__device__ float  g_Bb[B_ * H_ * 4];             // [b][j][g]

// ---------------- helpers ----------------
__device__ __forceinline__ unsigned long long pack2(float lo, float hi) {
    unsigned long long r;
    asm("mov.b64 %0, {%1,%2};" : "=l"(r) : "f"(lo), "f"(hi));
    return r;
}
__device__ __forceinline__ float hadd2(unsigned long long v) {
    float lo, hi;
    asm("mov.b64 {%0,%1}, %2;" : "=f"(lo), "=f"(hi) : "l"(v));
    return lo + hi;
}
__device__ __forceinline__ void fma2(unsigned long long& d,
                                     unsigned long long a,
                                     unsigned long long b) {
    asm("fma.rn.f32x2 %0, %1, %2, %0;" : "+l"(d) : "l"(a), "l"(b));
}
__device__ __forceinline__ float ex2a(float x) {
    float r; asm("ex2.approx.f32 %0, %1;" : "=f"(r) : "f"(x)); return r;
}
__device__ __forceinline__ float rcpa(float x) {
    float r; asm("rcp.approx.f32 %0, %1;" : "=f"(r) : "f"(x)); return r;
}
__device__ __forceinline__ float sig_a(float x) {
    return rcpa(1.0f + ex2a(-1.4426950408889634f * x));
}
__device__ __forceinline__ float tanh_a(float x) {
    float e = ex2a(2.8853900817779268f * x);
    return fmaf(-2.0f, rcpa(e + 1.0f), 1.0f);
}

// ============ prep: meta + both MLP layers (unchanged from round 8) ============
struct PrepSM {
    float meta[B_ * E_];     // 8 KB
    float hs[B_ * LH_];      // 32 KB
    float buf[LH_ * 64];     // 32 KB (holds W1 first, then W2 tile)
};

__global__ void prep_kernel(const float* __restrict__ x,
                            const float* __restrict__ wxW1, const float* __restrict__ wxB1,
                            const float* __restrict__ wxW2, const float* __restrict__ wxB2,
                            const float* __restrict__ whW1, const float* __restrict__ whB1,
                            const float* __restrict__ whW2, const float* __restrict__ whB2,
                            const float* __restrict__ lbW1, const float* __restrict__ lbB1,
                            const float* __restrict__ lbW2, const float* __restrict__ lbB2) {
    extern __shared__ char praw[];
    PrepSM* s = (PrepSM*)praw;
    int g  = blockIdx.x / 66;
    int tl = blockIdx.x % 66;
    int m  = (tl < 64) ? 1 : (tl == 64 ? 0 : 2);
    int tile = (m == 1) ? tl : 0;
    int tid = threadIdx.x;

    const float* W1; const float* b1; const float* W2; const float* b2; int ostride;
    if (m == 1)      { W1 = whW1; b1 = whB1; W2 = whW2 + g * LH_ * 4096 + tile * 64; b2 = whB2 + g * 4096 + tile * 64; ostride = 4096; }
    else if (m == 0) { W1 = wxW1; b1 = wxB1; W2 = wxW2 + g * LH_ * 64;               b2 = wxB2 + g * 64;               ostride = 64; }
    else             { W1 = lbW1; b1 = lbB1; W2 = lbW2 + g * LH_ * 64;               b2 = lbB2 + g * 64;               ostride = 64; }

#pragma unroll
    for (int i = 0; i < 8; i++) {
        int idx = tid + i * 256;
        int b = idx >> 5, e = idx & 31;
        float sum = 0.f;
#pragma unroll
        for (int t = 0; t < T_; t++)
            sum += x[(size_t)((b * T_ + t) * N_) * C_ + MOFF + e];
        s->meta[idx] = sum * (1.0f / 12.0f);
    }
    const float* W1g = W1 + g * E_ * LH_;
    for (int i = tid; i < E_ * LH_; i += 256) s->buf[i] = W1g[i];
    __syncthreads();

#pragma unroll
    for (int i = 0; i < 32; i++) {
        int idx = tid + i * 256;
        int b = idx >> 7, l = idx & 127;
        float acc = b1[g * LH_ + l];
#pragma unroll
        for (int e = 0; e < E_; e++)
            acc = fmaf(s->meta[b * E_ + e], s->buf[e * LH_ + l], acc);
        s->hs[idx] = fmaxf(acc, 0.f);
    }
    __syncthreads();

    for (int i = tid; i < LH_ * 64; i += 256) {
        int k = i >> 6, oo = i & 63;
        s->buf[i] = W2[k * ostride + oo];
    }
    __syncthreads();

    int o = tid & 63, bg = tid >> 6;
    float bv = b2[o];
    float acc[16];
#pragma unroll
    for (int i = 0; i < 16; i++) acc[i] = bv;
    const float* hb = s->hs + bg * 16 * LH_;
#pragma unroll 4
    for (int k = 0; k < LH_; k++) {
        float w = s->buf[k * 64 + o];
#pragma unroll
        for (int i = 0; i < 16; i++)
            acc[i] = fmaf(hb[i * LH_ + k], w, acc[i]);
    }

#pragma unroll
    for (int i = 0; i < 16; i++) {
        int b = bg * 16 + i;
        if (m == 0)      g_Wx[(b * H_ + o) * 4 + g] = acc[i];
        else if (m == 2) g_Bb[(b * H_ + o) * 4 + g] = acc[i];
        else {
            float* base = (g < 2) ? (float*)g_WhA[b] : (float*)g_WhB[b];
            base[(((tile >> 1) * 64) + o) * 4 + ((g & 1) << 1) + (tile & 1)] = acc[i];
        }
    }
}

// ============ LSTM recurrence + output head ============
struct SMEM {
    float4 WA[32 * 64];        // 32 KB  gates 0,1
    float4 WB[32 * 64];        // 32 KB  gates 2,3
    float  h[2][ROWS][H_];     // 20 KB  double-buffered
    float  xs[ROWS][T_];       // 1.875 KB
    float4 wx[H_];             // 1 KB
    float4 bi[H_];             // 1 KB
};

__global__ void __launch_bounds__(THR, 2)
lstm_kernel(const float* __restrict__ x,
            const float* __restrict__ fc1W, const float* __restrict__ fc1b,
            const float* __restrict__ fc2W, const float* __restrict__ fc2b,
            float* __restrict__ out) {
    extern __shared__ char smraw[];
    SMEM* s = (SMEM*)smraw;
    int b  = blockIdx.y;
    int n0 = blockIdx.x * ROWS;
    int tid = threadIdx.x;

    const float4* srcA = g_WhA[b];
    const float4* srcB = g_WhB[b];
    for (int i = tid; i < 32 * 64; i += THR) { s->WA[i] = srcA[i]; s->WB[i] = srcB[i]; }
    for (int i = tid; i < ROWS * T_; i += THR) {
        int r = i / T_, t = i - r * T_;
        int n = n0 + r;
        s->xs[r][t] = (n < N_) ? x[(size_t)((b * T_ + t) * N_ + n) * C_] : 0.f;
    }
    for (int i = tid; i < ROWS * H_; i += THR) ((float*)s->h[0])[i] = 0.f;
    if (tid < H_) {
        s->wx[tid] = *(const float4*)&g_Wx[(b * H_ + tid) * 4];
        s->bi[tid] = *(const float4*)&g_Bb[(b * H_ + tid) * 4];
    }
    __syncthreads();

    int w = tid >> 5, lane = tid & 31;
    int j  = ((w & 1) << 5) | lane;   // output index 0..63
    int r0 = (w >> 1) * 8;            // row-group base (8 rows)

    float c[8];
#pragma unroll
    for (int r = 0; r < 8; r++) c[r] = 0.f;

    int p = 0;
    for (int t = 0; t < T_; t++) {
        float4 wx4 = s->wx[j];
        float4 bi4 = s->bi[j];
        unsigned long long z0[8], z1[8], z2[8], z3[8];
#pragma unroll
        for (int r = 0; r < 8; r++) {
            float xv = s->xs[r0 + r][t];
            z0[r] = pack2(fmaf(xv, wx4.x, bi4.x), 0.f);
            z1[r] = pack2(fmaf(xv, wx4.y, bi4.y), 0.f);
            z2[r] = pack2(fmaf(xv, wx4.z, bi4.z), 0.f);
            z3[r] = pack2(fmaf(xv, wx4.w, bi4.w), 0.f);
        }
        const float* hbase = &s->h[p][0][0];
        // q = k-quad (k = 4q..4q+3). One LDS.128 of h feeds 8 FFMA2.
#pragma unroll 4
        for (int q = 0; q < 16; q++) {
            ulonglong2 a0 = *(const ulonglong2*)&s->WA[(2 * q)     * 64 + j];
            ulonglong2 a1 = *(const ulonglong2*)&s->WA[(2 * q + 1) * 64 + j];
            ulonglong2 b0 = *(const ulonglong2*)&s->WB[(2 * q)     * 64 + j];
            ulonglong2 b1 = *(const ulonglong2*)&s->WB[(2 * q + 1) * 64 + j];
#pragma unroll
            for (int r = 0; r < 8; r++) {
                ulonglong2 h2 =
                    *(const ulonglong2*)&hbase[(r0 + r) * H_ + 4 * q];
                fma2(z0[r], a0.x, h2.x);
                fma2(z0[r], a1.x, h2.y);
                fma2(z1[r], a0.y, h2.x);
                fma2(z1[r], a1.y, h2.y);
                fma2(z2[r], b0.x, h2.x);
                fma2(z2[r], b1.x, h2.y);
                fma2(z3[r], b0.y, h2.x);
                fma2(z3[r], b1.y, h2.y);
            }
        }
#pragma unroll
        for (int r = 0; r < 8; r++) {
            float gg = tanh_a(hadd2(z0[r]));
            float ii = sig_a(hadd2(z1[r]));
            float ff = sig_a(hadd2(z2[r]));
            float oo = sig_a(hadd2(z3[r]));
            float cc = fmaf(gg, ii, c[r] * ff);
            c[r] = cc;
            s->h[p ^ 1][r0 + r][j] = tanh_a(cc) * oo;
        }
        __syncthreads();
        p ^= 1;
    }

    // ---- output head: relu(h) @ fc1 -> relu -> @ fc2 ----
#pragma unroll
    for (int q = 0; q < 4; q++) {
        int row = w + 10 * q;
        int n = n0 + row;
        float acc = fc1b[lane];
#pragma unroll 16
        for (int i = 0; i < 64; i++) {
            float hv = fmaxf(s->h[p][row][i], 0.f);
            acc = fmaf(hv, fc1W[i * 32 + lane], acc);
        }
        float o1 = fmaxf(acc, 0.f);
        float acc2 = (lane < OUT_) ? fc2b[lane] : 0.f;
#pragma unroll
        for (int jj = 0; jj < 32; jj++) {
            float v  = __shfl_sync(0xffffffffu, o1, jj);
            float wv = (lane < OUT_) ? fc2W[jj * OUT_ + lane] : 0.f;
            acc2 = fmaf(v, wv, acc2);
        }
        if (lane < OUT_ && n < N_)
            out[(size_t)(b * OUT_ + lane) * N_ + n] = acc2;
    }
}

// ---------------- launcher ----------------
extern "C" void kernel_launch(void* const* d_in, const int* in_sizes, int n_in,
                              void* d_out, int out_size) {
    const float* x      = (const float*)d_in[0];
    const float* lwx_W1 = (const float*)d_in[1];
    const float* lwx_b1 = (const float*)d_in[2];
    const float* lwx_W2 = (const float*)d_in[3];
    const float* lwx_b2 = (const float*)d_in[4];
    const float* lwh_W1 = (const float*)d_in[5];
    const float* lwh_b1 = (const float*)d_in[6];
    const float* lwh_W2 = (const float*)d_in[7];
    const float* lwh_b2 = (const float*)d_in[8];
    const float* lb_W1  = (const float*)d_in[9];
    const float* lb_b1  = (const float*)d_in[10];
    const float* lb_W2  = (const float*)d_in[11];
    const float* lb_b2  = (const float*)d_in[12];
    const float* fc1W   = (const float*)d_in[13];
    const float* fc1b   = (const float*)d_in[14];
    const float* fc2W   = (const float*)d_in[15];
    const float* fc2b   = (const float*)d_in[16];

    cudaFuncSetAttribute(prep_kernel,
                         cudaFuncAttributeMaxDynamicSharedMemorySize,
                         (int)sizeof(PrepSM));
    cudaFuncSetAttribute(lstm_kernel,
                         cudaFuncAttributeMaxDynamicSharedMemorySize,
                         (int)sizeof(SMEM));

    prep_kernel<<<4 * 66, 256, sizeof(PrepSM)>>>(
        x, lwx_W1, lwx_b1, lwx_W2, lwx_b2,
           lwh_W1, lwh_b1, lwh_W2, lwh_b2,
           lb_W1,  lb_b1,  lb_W2,  lb_b2);

    dim3 grid(NBLK, B_);
    lstm_kernel<<<grid, THR, sizeof(SMEM)>>>(x, fc1W, fc1b, fc2W, fc2b,
                                             (float*)d_out);
}

// round 13
// speedup vs baseline: 1.6687x; 1.1916x over previous
#include <cuda_runtime.h>
#include <cuda_bf16.h>
#include <cstdint>

// ---------------- problem constants ----------------
constexpr int B_   = 64;
constexpr int T_   = 12;
constexpr int N_   = 325;
constexpr int E_   = 32;
constexpr int LH_  = 128;
constexpr int OUT_ = 12;
constexpr int C_   = 97;
constexpr int MOFF = 65;

constexpr int KP   = 146;   // padded k length (144 data + 2 pad; 73-word rows -> conflict-light)
constexpr int MT   = 64;    // rows per CTA
constexpr int NBLK = (N_ + MT - 1) / MT;   // 6 -> grid 384

// B operand per batch: [n=256][k=KP] bf16.  k: 0..63 Whi, 64..127 Wlo,
// 128=wxh 129=wxh 130=wxl 131=bh 132=bl 133..145 zero
__device__ __align__(16) unsigned char g_B[B_][256 * KP * 2];

// ---------------- helpers ----------------
__device__ __forceinline__ float ex2a(float x) {
    float r; asm("ex2.approx.f32 %0, %1;" : "=f"(r) : "f"(x)); return r;
}
__device__ __forceinline__ float rcpa(float x) {
    float r; asm("rcp.approx.f32 %0, %1;" : "=f"(r) : "f"(x)); return r;
}
__device__ __forceinline__ float sig_a(float x) {
    return rcpa(1.0f + ex2a(-1.4426950408889634f * x));
}
__device__ __forceinline__ float tanh_a(float x) {
    float e = ex2a(2.8853900817779268f * x);
    return fmaf(-2.0f, rcpa(e + 1.0f), 1.0f);
}
__device__ __forceinline__ void mma_bf16(float& d0, float& d1, float& d2, float& d3,
                                         uint32_t a0, uint32_t a1, uint32_t a2, uint32_t a3,
                                         uint32_t b0, uint32_t b1) {
    asm volatile("mma.sync.aligned.m16n8k16.row.col.f32.bf16.bf16.f32 "
                 "{%0,%1,%2,%3},{%4,%5,%6,%7},{%8,%9},{%0,%1,%2,%3};"
                 : "+f"(d0), "+f"(d1), "+f"(d2), "+f"(d3)
                 : "r"(a0), "r"(a1), "r"(a2), "r"(a3), "r"(b0), "r"(b1));
}
__device__ __forceinline__ uint32_t ld32(const __nv_bfloat16* p) {
    return *(const uint32_t*)p;
}
__device__ __forceinline__ uint32_t packbf(float a, float b) {
    __nv_bfloat16 ha = __float2bfloat16(a), hb = __float2bfloat16(b);
    return (uint32_t)__bfloat16_as_ushort(ha) |
           ((uint32_t)__bfloat16_as_ushort(hb) << 16);
}

// ============ prep: meta + both MLP layers -> g_B ============
struct PrepSM {
    float meta[B_ * E_];     // 8 KB
    float hs[B_ * LH_];      // 32 KB
    float buf[LH_ * 64];     // 32 KB
};

__global__ void prep_kernel(const float* __restrict__ x,
                            const float* __restrict__ wxW1, const float* __restrict__ wxB1,
                            const float* __restrict__ wxW2, const float* __restrict__ wxB2,
                            const float* __restrict__ whW1, const float* __restrict__ whB1,
                            const float* __restrict__ whW2, const float* __restrict__ whB2,
                            const float* __restrict__ lbW1, const float* __restrict__ lbB1,
                            const float* __restrict__ lbW2, const float* __restrict__ lbB2) {
    extern __shared__ char praw[];
    PrepSM* s = (PrepSM*)praw;
    int g  = blockIdx.x / 66;
    int tl = blockIdx.x % 66;
    int m  = (tl < 64) ? 1 : (tl == 64 ? 0 : 2);
    int tile = (m == 1) ? tl : 0;
    int tid = threadIdx.x;

    const float* W1; const float* b1; const float* W2; const float* b2; int ostride;
    if (m == 1)      { W1 = whW1; b1 = whB1; W2 = whW2 + g * LH_ * 4096 + tile * 64; b2 = whB2 + g * 4096 + tile * 64; ostride = 4096; }
    else if (m == 0) { W1 = wxW1; b1 = wxB1; W2 = wxW2 + g * LH_ * 64;               b2 = wxB2 + g * 64;               ostride = 64; }
    else             { W1 = lbW1; b1 = lbB1; W2 = lbW2 + g * LH_ * 64;               b2 = lbB2 + g * 64;               ostride = 64; }

#pragma unroll
    for (int i = 0; i < 8; i++) {
        int idx = tid + i * 256;
        int b = idx >> 5, e = idx & 31;
        float sum = 0.f;
#pragma unroll
        for (int t = 0; t < T_; t++)
            sum += x[(size_t)((b * T_ + t) * N_) * C_ + MOFF + e];
        s->meta[idx] = sum * (1.0f / 12.0f);
    }
    const float* W1g = W1 + g * E_ * LH_;
    for (int i = tid; i < E_ * LH_; i += 256) s->buf[i] = W1g[i];
    __syncthreads();

#pragma unroll
    for (int i = 0; i < 32; i++) {
        int idx = tid + i * 256;
        int b = idx >> 7, l = idx & 127;
        float acc = b1[g * LH_ + l];
#pragma unroll
        for (int e = 0; e < E_; e++)
            acc = fmaf(s->meta[b * E_ + e], s->buf[e * LH_ + l], acc);
        s->hs[idx] = fmaxf(acc, 0.f);
    }
    __syncthreads();

    for (int i = tid; i < LH_ * 64; i += 256) {
        int k = i >> 6, oo = i & 63;
        s->buf[i] = W2[k * ostride + oo];
    }
    __syncthreads();

    int o = tid & 63, bg = tid >> 6;
    float bv = b2[o];
    float acc[16];
#pragma unroll
    for (int i = 0; i < 16; i++) acc[i] = bv;
    const float* hb = s->hs + bg * 16 * LH_;
#pragma unroll 4
    for (int k = 0; k < LH_; k++) {
        float w = s->buf[k * 64 + o];
#pragma unroll
        for (int i = 0; i < 16; i++)
            acc[i] = fmaf(hb[i * LH_ + k], w, acc[i]);
    }

    int nrow = g * 64 + o;
    __nv_bfloat16 zz = __float2bfloat16(0.f);
#pragma unroll
    for (int i = 0; i < 16; i++) {
        int b = bg * 16 + i;
        float v = acc[i];
        __nv_bfloat16 hi = __float2bfloat16(v);
        __nv_bfloat16 lo = __float2bfloat16(v - __bfloat162float(hi));
        __nv_bfloat16* dst = (__nv_bfloat16*)g_B[b] + nrow * KP;
        if (m == 1) {
            dst[tile]      = hi;   // Whi
            dst[64 + tile] = lo;   // Wlo
        } else if (m == 0) {
            dst[128] = hi;         // pairs with xh
            dst[129] = hi;         // pairs with xl
            dst[130] = lo;         // pairs with xh
            for (int k = 133; k < KP; k++) dst[k] = zz;
        } else {
            dst[131] = hi;         // bh (pairs with 1)
            dst[132] = lo;         // bl (pairs with 1)
        }
    }
}

// ============ LSTM via mma.sync (HMMA bf16, split hi/lo) ============
struct LSM {
    __nv_bfloat16 Bs[256 * KP];   // 74752 B
    __nv_bfloat16 As[MT * KP];    // 18688 B
    float P[64 * 64];             // 16384 B  (P exchange; final h)
    float xs[MT * T_];            // 3072 B
};
// total 112896 B -> 2 CTAs/SM

__global__ void __launch_bounds__(256, 2)
lstm_kernel(const float* __restrict__ x,
            const float* __restrict__ fc1W, const float* __restrict__ fc1b,
            const float* __restrict__ fc2W, const float* __restrict__ fc2b,
            float* __restrict__ out) {
    extern __shared__ __align__(16) char smraw[];
    LSM* s = (LSM*)smraw;
    int b   = blockIdx.y;
    int n0  = blockIdx.x * MT;
    int tid = threadIdx.x;
    int w = tid >> 5, lane = tid & 31;
    int wm = w & 3, wn = w >> 2;          // wm: m-tile(16 rows), wn: N-half
    int tq = lane >> 2, tr = lane & 3;

    // ---- stage B, zero A, stage x ----
    {
        const uint4* gb = (const uint4*)g_B[b];
        uint4* sb = (uint4*)s->Bs;
        for (int i = tid; i < 256 * KP * 2 / 16; i += 256) sb[i] = gb[i];
        uint4 z4 = make_uint4(0, 0, 0, 0);
        uint4* sa = (uint4*)s->As;
        for (int i = tid; i < MT * KP * 2 / 16; i += 256) sa[i] = z4;
        for (int i = tid; i < MT * T_; i += 256) {
            int m = i / T_, t = i - m * T_;
            int n = n0 + m;
            s->xs[i] = (n < N_) ? x[(size_t)((b * T_ + t) * N_ + n) * C_] : 0.f;
        }
    }
    __syncthreads();
    if (tid < MT) {   // const cols + x(t=0)
        __nv_bfloat16 one = __float2bfloat16(1.0f);
        __nv_bfloat16* ar = s->As + tid * KP;
        ar[131] = one; ar[132] = one;
        float xv = s->xs[tid * T_];
        __nv_bfloat16 xh = __float2bfloat16(xv);
        __nv_bfloat16 xl = __float2bfloat16(xv - __bfloat162float(xh));
        ar[128] = xh; ar[129] = xl; ar[130] = xh;
    }

    const __nv_bfloat16* aRow0 = s->As + (wm * 16 + tq) * KP;
    const __nv_bfloat16* aRow8 = aRow0 + 8 * KP;
    const __nv_bfloat16* bBase = s->Bs + (wn * 128 + tq) * KP + 2 * tr;

    float cst[32];
#pragma unroll
    for (int i = 0; i < 32; i++) cst[i] = 0.f;

    for (int t = 0; t < T_; t++) {
        __syncthreads();   // A (h_{t-1}, x_t) ready

        float d0[16], d1[16], d2[16], d3[16];
#pragma unroll
        for (int nt = 0; nt < 16; nt++) { d0[nt] = d1[nt] = d2[nt] = d3[nt] = 0.f; }

        // pass 1: hh@Whi + hl@Whi   (kB = 0..63)
#pragma unroll
        for (int cc = 0; cc < 4; cc++) {
            int ka = cc * 16 + 2 * tr;
            uint32_t h0 = ld32(aRow0 + ka),      h1 = ld32(aRow8 + ka);
            uint32_t h2 = ld32(aRow0 + ka + 8),  h3 = ld32(aRow8 + ka + 8);
            uint32_t l0 = ld32(aRow0 + 64 + ka), l1 = ld32(aRow8 + 64 + ka);
            uint32_t l2 = ld32(aRow0 + 72 + ka), l3 = ld32(aRow8 + 72 + ka);
#pragma unroll
            for (int nt = 0; nt < 16; nt++) {
                const __nv_bfloat16* bp = bBase + nt * 8 * KP + cc * 16;
                uint32_t b0 = ld32(bp), b1 = ld32(bp + 8);
                mma_bf16(d0[nt], d1[nt], d2[nt], d3[nt], h0, h1, h2, h3, b0, b1);
                mma_bf16(d0[nt], d1[nt], d2[nt], d3[nt], l0, l1, l2, l3, b0, b1);
            }
        }
        // pass 2: hh@Wlo   (kB = 64..127)
#pragma unroll
        for (int cc = 0; cc < 4; cc++) {
            int ka = cc * 16 + 2 * tr;
            uint32_t h0 = ld32(aRow0 + ka),     h1 = ld32(aRow8 + ka);
            uint32_t h2 = ld32(aRow0 + ka + 8), h3 = ld32(aRow8 + ka + 8);
#pragma unroll
            for (int nt = 0; nt < 16; nt++) {
                const __nv_bfloat16* bp = bBase + nt * 8 * KP + 64 + cc * 16;
                uint32_t b0 = ld32(bp), b1 = ld32(bp + 8);
                mma_bf16(d0[nt], d1[nt], d2[nt], d3[nt], h0, h1, h2, h3, b0, b1);
            }
        }
        // pass 3: x-block (kA = kB = 128..143)
        {
            int ka = 128 + 2 * tr;
            uint32_t a0 = ld32(aRow0 + ka),     a1 = ld32(aRow8 + ka);
            uint32_t a2 = ld32(aRow0 + ka + 8), a3 = ld32(aRow8 + ka + 8);
#pragma unroll
            for (int nt = 0; nt < 16; nt++) {
                const __nv_bfloat16* bp = bBase + nt * 8 * KP + 128;
                uint32_t b0 = ld32(bp), b1 = ld32(bp + 8);
                mma_bf16(d0[nt], d1[nt], d2[nt], d3[nt], a0, a1, a2, a3, b0, b1);
            }
        }

        int m1 = wm * 16 + tq, m2 = m1 + 8;

        if (wn == 0) {
            // gates g (nt 0..7) and i (nt 8..15): P = tanh(zg)*sig(zi)
#pragma unroll
            for (int nt = 0; nt < 8; nt++) {
                int j0 = nt * 8 + 2 * tr;
                s->P[j0 * 64 + m1]       = tanh_a(d0[nt]) * sig_a(d0[nt + 8]);
                s->P[(j0 + 1) * 64 + m1] = tanh_a(d1[nt]) * sig_a(d1[nt + 8]);
                s->P[j0 * 64 + m2]       = tanh_a(d2[nt]) * sig_a(d2[nt + 8]);
                s->P[(j0 + 1) * 64 + m2] = tanh_a(d3[nt]) * sig_a(d3[nt + 8]);
            }
        }
        __syncthreads();   // P visible; all A reads done

        if (wn == 0) {
            if (lane < 16 && t < T_ - 1) {    // write x(t+1)
                int m = wm * 16 + lane;
                float xv = s->xs[m * T_ + t + 1];
                __nv_bfloat16 xh = __float2bfloat16(xv);
                __nv_bfloat16 xl = __float2bfloat16(xv - __bfloat162float(xh));
                __nv_bfloat16* ar = s->As + m * KP;
                ar[128] = xh; ar[129] = xl; ar[130] = xh;
            }
        } else {
            // gates f (nt 0..7) and o (nt 8..15): c,h update
#pragma unroll
            for (int nt = 0; nt < 8; nt++) {
                int j0 = nt * 8 + 2 * tr;
                float F0 = sig_a(d0[nt]), O0 = sig_a(d0[nt + 8]);
                float F1 = sig_a(d1[nt]), O1 = sig_a(d1[nt + 8]);
                float F2 = sig_a(d2[nt]), O2 = sig_a(d2[nt + 8]);
                float F3 = sig_a(d3[nt]), O3 = sig_a(d3[nt + 8]);
                float c0 = fmaf(cst[nt * 4 + 0], F0, s->P[j0 * 64 + m1]);
                float c1 = fmaf(cst[nt * 4 + 1], F1, s->P[(j0 + 1) * 64 + m1]);
                float c2 = fmaf(cst[nt * 4 + 2], F2, s->P[j0 * 64 + m2]);
                float c3 = fmaf(cst[nt * 4 + 3], F3, s->P[(j0 + 1) * 64 + m2]);
                cst[nt * 4 + 0] = c0; cst[nt * 4 + 1] = c1;
                cst[nt * 4 + 2] = c2; cst[nt * 4 + 3] = c3;
                float h0 = tanh_a(c0) * O0, h1 = tanh_a(c1) * O1;
                float h2 = tanh_a(c2) * O2, h3 = tanh_a(c3) * O3;
                if (t < T_ - 1) {
                    // h hi at A[m][j0], lo at A[m][64+j0]
                    __nv_bfloat16 b0h = __float2bfloat16(h0);
                    __nv_bfloat16 b1h = __float2bfloat16(h1);
                    __nv_bfloat16 b2h = __float2bfloat16(h2);
                    __nv_bfloat16 b3h = __float2bfloat16(h3);
                    uint32_t ph12 = (uint32_t)__bfloat16_as_ushort(b0h) |
                                    ((uint32_t)__bfloat16_as_ushort(b1h) << 16);
                    uint32_t ph34 = (uint32_t)__bfloat16_as_ushort(b2h) |
                                    ((uint32_t)__bfloat16_as_ushort(b3h) << 16);
                    uint32_t pl12 = packbf(h0 - __bfloat162float(b0h),
                                           h1 - __bfloat162float(b1h));
                    uint32_t pl34 = packbf(h2 - __bfloat162float(b2h),
                                           h3 - __bfloat162float(b3h));
                    *(uint32_t*)(s->As + m1 * KP + j0)      = ph12;
                    *(uint32_t*)(s->As + m2 * KP + j0)      = ph34;
                    *(uint32_t*)(s->As + m1 * KP + 64 + j0) = pl12;
                    *(uint32_t*)(s->As + m2 * KP + 64 + j0) = pl34;
                } else {
                    // final h (fp32) into P for the head
                    s->P[j0 * 64 + m1]       = h0;
                    s->P[(j0 + 1) * 64 + m1] = h1;
                    s->P[j0 * 64 + m2]       = h2;
                    s->P[(j0 + 1) * 64 + m2] = h3;
                }
            }
        }
    }
    __syncthreads();   // final h visible

    // ---- output head: relu(h) @ fc1 -> relu -> @ fc2 ----
#pragma unroll
    for (int q = 0; q < 8; q++) {
        int row = w * 8 + q;
        int n = n0 + row;
        float acc = fc1b[lane];
#pragma unroll 16
        for (int i = 0; i < 64; i++) {
            float hv = fmaxf(s->P[i * 64 + row], 0.f);
            acc = fmaf(hv, fc1W[i * 32 + lane], acc);
        }
        float o1 = fmaxf(acc, 0.f);
        float acc2 = (lane < OUT_) ? fc2b[lane] : 0.f;
#pragma unroll
        for (int jj = 0; jj < 32; jj++) {
            float v  = __shfl_sync(0xffffffffu, o1, jj);
            float wv = (lane < OUT_) ? fc2W[jj * OUT_ + lane] : 0.f;
            acc2 = fmaf(v, wv, acc2);
        }
        if (lane < OUT_ && n < N_)
            out[(size_t)(b * OUT_ + lane) * N_ + n] = acc2;
    }
}

// ---------------- launcher ----------------
extern "C" void kernel_launch(void* const* d_in, const int* in_sizes, int n_in,
                              void* d_out, int out_size) {
    const float* x      = (const float*)d_in[0];
    const float* lwx_W1 = (const float*)d_in[1];
    const float* lwx_b1 = (const float*)d_in[2];
    const float* lwx_W2 = (const float*)d_in[3];
    const float* lwx_b2 = (const float*)d_in[4];
    const float* lwh_W1 = (const float*)d_in[5];
    const float* lwh_b1 = (const float*)d_in[6];
    const float* lwh_W2 = (const float*)d_in[7];
    const float* lwh_b2 = (const float*)d_in[8];
    const float* lb_W1  = (const float*)d_in[9];
    const float* lb_b1  = (const float*)d_in[10];
    const float* lb_W2  = (const float*)d_in[11];
    const float* lb_b2  = (const float*)d_in[12];
    const float* fc1W   = (const float*)d_in[13];
    const float* fc1b   = (const float*)d_in[14];
    const float* fc2W   = (const float*)d_in[15];
    const float* fc2b   = (const float*)d_in[16];

    cudaFuncSetAttribute(prep_kernel,
                         cudaFuncAttributeMaxDynamicSharedMemorySize,
                         (int)sizeof(PrepSM));
    cudaFuncSetAttribute(lstm_kernel,
                         cudaFuncAttributeMaxDynamicSharedMemorySize,
                         (int)sizeof(LSM));

    prep_kernel<<<4 * 66, 256, sizeof(PrepSM)>>>(
        x, lwx_W1, lwx_b1, lwx_W2, lwx_b2,
           lwh_W1, lwh_b1, lwh_W2, lwh_b2,
           lb_W1,  lb_b1,  lb_W2,  lb_b2);

    dim3 grid(NBLK, B_);
    lstm_kernel<<<grid, 256, sizeof(LSM)>>>(x, fc1W, fc1b, fc2W, fc2b,
                                            (float*)d_out);
}

// round 15
// speedup vs baseline: 2.3820x; 1.4275x over previous
#include <cuda_runtime.h>
#include <cuda_bf16.h>
#include <cstdint>

// ---------------- problem constants ----------------
constexpr int B_   = 64;
constexpr int T_   = 12;
constexpr int N_   = 325;
constexpr int E_   = 32;
constexpr int LH_  = 128;
constexpr int OUT_ = 12;
constexpr int C_   = 97;
constexpr int MOFF = 65;

constexpr int KP   = 152;   // padded k: 144 data + 8 pad; 304B row stride (16B-aligned, conflict-free ldmatrix)
constexpr int MT   = 64;    // rows per CTA
constexpr int NBLK = (N_ + MT - 1) / MT;   // 6 -> grid 384

// B operand per batch: [n=256][k=KP] bf16.  k: 0..63 Whi, 64..127 Wlo,
// 128=wxh 129=wxh 130=wxl 131=bh 132=bl 133..151 zero
__device__ __align__(16) unsigned char g_B[B_][256 * KP * 2];

// ---------------- helpers ----------------
__device__ __forceinline__ float ex2a(float x) {
    float r; asm("ex2.approx.f32 %0, %1;" : "=f"(r) : "f"(x)); return r;
}
__device__ __forceinline__ float rcpa(float x) {
    float r; asm("rcp.approx.f32 %0, %1;" : "=f"(r) : "f"(x)); return r;
}
__device__ __forceinline__ float sig_a(float x) {
    return rcpa(1.0f + ex2a(-1.4426950408889634f * x));
}
__device__ __forceinline__ float tanh_a(float x) {
    float e = ex2a(2.8853900817779268f * x);
    return fmaf(-2.0f, rcpa(e + 1.0f), 1.0f);
}
__device__ __forceinline__ void mma_bf16(float& d0, float& d1, float& d2, float& d3,
                                         uint32_t a0, uint32_t a1, uint32_t a2, uint32_t a3,
                                         uint32_t b0, uint32_t b1) {
    asm volatile("mma.sync.aligned.m16n8k16.row.col.f32.bf16.bf16.f32 "
                 "{%0,%1,%2,%3},{%4,%5,%6,%7},{%8,%9},{%0,%1,%2,%3};"
                 : "+f"(d0), "+f"(d1), "+f"(d2), "+f"(d3)
                 : "r"(a0), "r"(a1), "r"(a2), "r"(a3), "r"(b0), "r"(b1));
}
__device__ __forceinline__ void ldm4(uint32_t& r0, uint32_t& r1,
                                     uint32_t& r2, uint32_t& r3, uint32_t a) {
    asm volatile("ldmatrix.sync.aligned.m8n8.x4.shared.b16 {%0,%1,%2,%3}, [%4];"
                 : "=r"(r0), "=r"(r1), "=r"(r2), "=r"(r3) : "r"(a));
}
__device__ __forceinline__ uint32_t smem_u32(const void* p) {
    uint32_t a;
    asm("{ .reg .u64 t; cvta.to.shared.u64 t, %1; cvt.u32.u64 %0, t; }" : "=r"(a) : "l"(p));
    return a;
}
__device__ __forceinline__ uint32_t packbf(float a, float b) {
    __nv_bfloat16 ha = __float2bfloat16(a), hb = __float2bfloat16(b);
    return (uint32_t)__bfloat16_as_ushort(ha) |
           ((uint32_t)__bfloat16_as_ushort(hb) << 16);
}

// ============ prep: meta + both MLP layers -> g_B ============
struct PrepSM {
    float meta[B_ * E_];
    float hs[B_ * LH_];
    float buf[LH_ * 64];
};

__global__ void prep_kernel(const float* __restrict__ x,
                            const float* __restrict__ wxW1, const float* __restrict__ wxB1,
                            const float* __restrict__ wxW2, const float* __restrict__ wxB2,
                            const float* __restrict__ whW1, const float* __restrict__ whB1,
                            const float* __restrict__ whW2, const float* __restrict__ whB2,
                            const float* __restrict__ lbW1, const float* __restrict__ lbB1,
                            const float* __restrict__ lbW2, const float* __restrict__ lbB2) {
    extern __shared__ char praw[];
    PrepSM* s = (PrepSM*)praw;
    int g  = blockIdx.x / 66;
    int tl = blockIdx.x % 66;
    int m  = (tl < 64) ? 1 : (tl == 64 ? 0 : 2);
    int tile = (m == 1) ? tl : 0;
    int tid = threadIdx.x;

    const float* W1; const float* b1; const float* W2; const float* b2; int ostride;
    if (m == 1)      { W1 = whW1; b1 = whB1; W2 = whW2 + g * LH_ * 4096 + tile * 64; b2 = whB2 + g * 4096 + tile * 64; ostride = 4096; }
    else if (m == 0) { W1 = wxW1; b1 = wxB1; W2 = wxW2 + g * LH_ * 64;               b2 = wxB2 + g * 64;               ostride = 64; }
    else             { W1 = lbW1; b1 = lbB1; W2 = lbW2 + g * LH_ * 64;               b2 = lbB2 + g * 64;               ostride = 64; }

#pragma unroll
    for (int i = 0; i < 8; i++) {
        int idx = tid + i * 256;
        int b = idx >> 5, e = idx & 31;
        float sum = 0.f;
#pragma unroll
        for (int t = 0; t < T_; t++)
            sum += x[(size_t)((b * T_ + t) * N_) * C_ + MOFF + e];
        s->meta[idx] = sum * (1.0f / 12.0f);
    }
    const float* W1g = W1 + g * E_ * LH_;
    for (int i = tid; i < E_ * LH_; i += 256) s->buf[i] = W1g[i];
    __syncthreads();

#pragma unroll
    for (int i = 0; i < 32; i++) {
        int idx = tid + i * 256;
        int b = idx >> 7, l = idx & 127;
        float acc = b1[g * LH_ + l];
#pragma unroll
        for (int e = 0; e < E_; e++)
            acc = fmaf(s->meta[b * E_ + e], s->buf[e * LH_ + l], acc);
        s->hs[idx] = fmaxf(acc, 0.f);
    }
    __syncthreads();

    for (int i = tid; i < LH_ * 64; i += 256) {
        int k = i >> 6, oo = i & 63;
        s->buf[i] = W2[k * ostride + oo];
    }
    __syncthreads();

    int o = tid & 63, bg = tid >> 6;
    float bv = b2[o];
    float acc[16];
#pragma unroll
    for (int i = 0; i < 16; i++) acc[i] = bv;
    const float* hb = s->hs + bg * 16 * LH_;
#pragma unroll 4
    for (int k = 0; k < LH_; k++) {
        float w = s->buf[k * 64 + o];
#pragma unroll
        for (int i = 0; i < 16; i++)
            acc[i] = fmaf(hb[i * LH_ + k], w, acc[i]);
    }

    int nrow = g * 64 + o;
    __nv_bfloat16 zz = __float2bfloat16(0.f);
#pragma unroll
    for (int i = 0; i < 16; i++) {
        int b = bg * 16 + i;
        float v = acc[i];
        __nv_bfloat16 hi = __float2bfloat16(v);
        __nv_bfloat16 lo = __float2bfloat16(v - __bfloat162float(hi));
        __nv_bfloat16* dst = (__nv_bfloat16*)g_B[b] + nrow * KP;
        if (m == 1) {
            dst[tile]      = hi;
            dst[64 + tile] = lo;
        } else if (m == 0) {
            dst[128] = hi;
            dst[129] = hi;
            dst[130] = lo;
            for (int k = 133; k < KP; k++) dst[k] = zz;
        } else {
            dst[131] = hi;
            dst[132] = lo;
        }
    }
}

// ============ LSTM via mma.sync: gate-local warps + ldmatrix ============
struct LSM {
    union {
        __nv_bfloat16 Bs[256 * KP];   // 77824 B (used through the last mma)
        float P[64 * 64];             // 16384 B (final h; written only after last B read)
    };
    __nv_bfloat16 As[MT * KP];        // 19456 B
    float xs[MT * T_];                // 3072 B
};
// total 100352 B -> 2 CTAs/SM

__global__ void __launch_bounds__(256, 2)
lstm_kernel(const float* __restrict__ x,
            const float* __restrict__ fc1W, const float* __restrict__ fc1b,
            const float* __restrict__ fc2W, const float* __restrict__ fc2b,
            float* __restrict__ out) {
    extern __shared__ __align__(16) char smraw[];
    LSM* s = (LSM*)smraw;
    int b   = blockIdx.y;
    int n0  = blockIdx.x * MT;
    int tid = threadIdx.x;
    int w = tid >> 5, lane = tid & 31;
    int wm = w & 3, wn = w >> 2;          // wm: m16-tile, wn: j32-half (all 4 gates local)
    int tq = lane >> 2, tr = lane & 3;

    // ---- stage B, zero A, stage x ----
    {
        const uint4* gb = (const uint4*)g_B[b];
        uint4* sb = (uint4*)s->Bs;
        for (int i = tid; i < 256 * KP * 2 / 16; i += 256) sb[i] = gb[i];
        uint4 z4 = make_uint4(0, 0, 0, 0);
        uint4* sa = (uint4*)s->As;
        for (int i = tid; i < MT * KP * 2 / 16; i += 256) sa[i] = z4;
        for (int i = tid; i < MT * T_; i += 256) {
            int m = i / T_, t = i - m * T_;
            int n = n0 + m;
            s->xs[i] = (n < N_) ? x[(size_t)((b * T_ + t) * N_ + n) * C_] : 0.f;
        }
    }
    __syncthreads();
    if (tid < MT) {   // const cols + x(t=0)
        __nv_bfloat16 one = __float2bfloat16(1.0f);
        __nv_bfloat16* ar = s->As + tid * KP;
        ar[131] = one; ar[132] = one;
        float xv = s->xs[tid * T_];
        __nv_bfloat16 xh = __float2bfloat16(xv);
        __nv_bfloat16 xl = __float2bfloat16(xv - __bfloat162float(xh));
        ar[128] = xh; ar[129] = xl; ar[130] = xh;
    }

    // ldmatrix per-lane addresses (all row starts 16B-aligned: KP*2 = 304 = 19*16)
    int arow  = (lane & 7) + (lane & 8);         // A tiles: m0k0, m8k0, m0k8, m8k8
    int akofs = (lane >= 16) ? 8 : 0;
    int brow  = (lane & 7) + ((lane >> 4) << 3); // B tiles: n0k0, n0k8, n8k0, n8k8
    int bkofs = (lane & 8);
    uint32_t sA = smem_u32(s->As) + (uint32_t)(((wm * 16 + arow) * KP + akofs) * 2);
    uint32_t sB = smem_u32(s->Bs) + (uint32_t)(((wn * 32 + brow) * KP + bkofs) * 2);

    float cst[16];
#pragma unroll
    for (int i = 0; i < 16; i++) cst[i] = 0.f;

    int m1 = wm * 16 + tq, m2 = m1 + 8;

    for (int t = 0; t < T_; t++) {
        __syncthreads();   // A (h_{t-1}, x_t) ready

        float d0[16], d1[16], d2[16], d3[16];   // nt = g*4 + ntj
#pragma unroll
        for (int nt = 0; nt < 16; nt++) { d0[nt] = d1[nt] = d2[nt] = d3[nt] = 0.f; }

        // k-chunks of hh/hl (kA = cc*16)
#pragma unroll
        for (int cc = 0; cc < 4; cc++) {
            uint32_t h0, h1, h2, h3, l0, l1, l2, l3;
            ldm4(h0, h1, h2, h3, sA + cc * 32);        // hh frags
            ldm4(l0, l1, l2, l3, sA + 128 + cc * 32);  // hl frags
#pragma unroll
            for (int g = 0; g < 4; g++)
#pragma unroll
                for (int p = 0; p < 2; p++) {
                    uint32_t bofs = (uint32_t)((g * 64 + p * 16) * KP * 2);
                    uint32_t b0, b1, b2, b3;
                    int n1 = g * 4 + 2 * p, n2 = n1 + 1;
                    // Whi chunk: hh + hl against it
                    ldm4(b0, b1, b2, b3, sB + bofs + cc * 32);
                    mma_bf16(d0[n1], d1[n1], d2[n1], d3[n1], h0, h1, h2, h3, b0, b1);
                    mma_bf16(d0[n1], d1[n1], d2[n1], d3[n1], l0, l1, l2, l3, b0, b1);
                    mma_bf16(d0[n2], d1[n2], d2[n2], d3[n2], h0, h1, h2, h3, b2, b3);
                    mma_bf16(d0[n2], d1[n2], d2[n2], d3[n2], l0, l1, l2, l3, b2, b3);
                    // Wlo chunk: hh only
                    ldm4(b0, b1, b2, b3, sB + bofs + 128 + cc * 32);
                    mma_bf16(d0[n1], d1[n1], d2[n1], d3[n1], h0, h1, h2, h3, b0, b1);
                    mma_bf16(d0[n2], d1[n2], d2[n2], d3[n2], h0, h1, h2, h3, b2, b3);
                }
        }
        // x-block (kA = kB = 128..143)
        {
            uint32_t a0, a1, a2, a3;
            ldm4(a0, a1, a2, a3, sA + 256);
#pragma unroll
            for (int g = 0; g < 4; g++)
#pragma unroll
                for (int p = 0; p < 2; p++) {
                    uint32_t bofs = (uint32_t)((g * 64 + p * 16) * KP * 2);
                    uint32_t b0, b1, b2, b3;
                    int n1 = g * 4 + 2 * p, n2 = n1 + 1;
                    ldm4(b0, b1, b2, b3, sB + bofs + 256);
                    mma_bf16(d0[n1], d1[n1], d2[n1], d3[n1], a0, a1, a2, a3, b0, b1);
                    mma_bf16(d0[n2], d1[n2], d2[n2], d3[n2], a0, a1, a2, a3, b2, b3);
                }
        }
        __syncthreads();   // all A/B reads done; safe to overwrite A (and P at t=T-1)

        // ---- warp-local epilogue: all 4 gates for (m16 x j32) ----
        if (wn == 0 && lane < 16 && t < T_ - 1) {   // x(t+1)
            int m = wm * 16 + lane;
            float xv = s->xs[m * T_ + t + 1];
            __nv_bfloat16 xh = __float2bfloat16(xv);
            __nv_bfloat16 xl = __float2bfloat16(xv - __bfloat162float(xh));
            __nv_bfloat16* ar = s->As + m * KP;
            ar[128] = xh; ar[129] = xl; ar[130] = xh;
        }
#pragma unroll
        for (int ntj = 0; ntj < 4; ntj++) {
            int jp = wn * 32 + ntj * 8 + 2 * tr;
            float G, I, F, O, cn;
            G = tanh_a(d0[ntj]);      I = sig_a(d0[4 + ntj]);
            F = sig_a(d0[8 + ntj]);   O = sig_a(d0[12 + ntj]);
            cn = fmaf(cst[ntj * 4 + 0], F, G * I); cst[ntj * 4 + 0] = cn;
            float h00 = tanh_a(cn) * O;
            G = tanh_a(d1[ntj]);      I = sig_a(d1[4 + ntj]);
            F = sig_a(d1[8 + ntj]);   O = sig_a(d1[12 + ntj]);
            cn = fmaf(cst[ntj * 4 + 1], F, G * I); cst[ntj * 4 + 1] = cn;
            float h01 = tanh_a(cn) * O;
            G = tanh_a(d2[ntj]);      I = sig_a(d2[4 + ntj]);
            F = sig_a(d2[8 + ntj]);   O = sig_a(d2[12 + ntj]);
            cn = fmaf(cst[ntj * 4 + 2], F, G * I); cst[ntj * 4 + 2] = cn;
            float h10 = tanh_a(cn) * O;
            G = tanh_a(d3[ntj]);      I = sig_a(d3[4 + ntj]);
            F = sig_a(d3[8 + ntj]);   O = sig_a(d3[12 + ntj]);
            cn = fmaf(cst[ntj * 4 + 3], F, G * I); cst[ntj * 4 + 3] = cn;
            float h11 = tanh_a(cn) * O;

            if (t < T_ - 1) {
                __nv_bfloat16 b00 = __float2bfloat16(h00);
                __nv_bfloat16 b01 = __float2bfloat16(h01);
                __nv_bfloat16 b10 = __float2bfloat16(h10);
                __nv_bfloat16 b11 = __float2bfloat16(h11);
                uint32_t hi0 = (uint32_t)__bfloat16_as_ushort(b00) |
                               ((uint32_t)__bfloat16_as_ushort(b01) << 16);
                uint32_t hi1 = (uint32_t)__bfloat16_as_ushort(b10) |
                               ((uint32_t)__bfloat16_as_ushort(b11) << 16);
                uint32_t lo0 = packbf(h00 - __bfloat162float(b00),
                                      h01 - __bfloat162float(b01));
                uint32_t lo1 = packbf(h10 - __bfloat162float(b10),
                                      h11 - __bfloat162float(b11));
                *(uint32_t*)(s->As + m1 * KP + jp)      = hi0;
                *(uint32_t*)(s->As + m1 * KP + 64 + jp) = lo0;
                *(uint32_t*)(s->As + m2 * KP + jp)      = hi1;
                *(uint32_t*)(s->As + m2 * KP + 64 + jp) = lo1;
            } else {
                s->P[jp * 64 + m1]       = h00;
                s->P[(jp + 1) * 64 + m1] = h01;
                s->P[jp * 64 + m2]       = h10;
                s->P[(jp + 1) * 64 + m2] = h11;
            }
        }
    }
    __syncthreads();   // final h visible

    // ---- output head: relu(h) @ fc1 -> relu -> @ fc2 ----
#pragma unroll
    for (int q = 0; q < 8; q++) {
        int row = w * 8 + q;
        int n = n0 + row;
        float acc = fc1b[lane];
#pragma unroll 16
        for (int i = 0; i < 64; i++) {
            float hv = fmaxf(s->P[i * 64 + row], 0.f);
            acc = fmaf(hv, fc1W[i * 32 + lane], acc);
        }
        float o1 = fmaxf(acc, 0.f);
        float acc2 = (lane < OUT_) ? fc2b[lane] : 0.f;
#pragma unroll
        for (int jj = 0; jj < 32; jj++) {
            float v  = __shfl_sync(0xffffffffu, o1, jj);
            float wv = (lane < OUT_) ? fc2W[jj * OUT_ + lane] : 0.f;
            acc2 = fmaf(v, wv, acc2);
        }
        if (lane < OUT_ && n < N_)
            out[(size_t)(b * OUT_ + lane) * N_ + n] = acc2;
    }
}

// ---------------- launcher ----------------
extern "C" void kernel_launch(void* const* d_in, const int* in_sizes, int n_in,
                              void* d_out, int out_size) {
    const float* x      = (const float*)d_in[0];
    const float* lwx_W1 = (const float*)d_in[1];
    const float* lwx_b1 = (const float*)d_in[2];
    const float* lwx_W2 = (const float*)d_in[3];
    const float* lwx_b2 = (const float*)d_in[4];
    const float* lwh_W1 = (const float*)d_in[5];
    const float* lwh_b1 = (const float*)d_in[6];
    const float* lwh_W2 = (const float*)d_in[7];
    const float* lwh_b2 = (const float*)d_in[8];
    const float* lb_W1  = (const float*)d_in[9];
    const float* lb_b1  = (const float*)d_in[10];
    const float* lb_W2  = (const float*)d_in[11];
    const float* lb_b2  = (const float*)d_in[12];
    const float* fc1W   = (const float*)d_in[13];
    const float* fc1b   = (const float*)d_in[14];
    const float* fc2W   = (const float*)d_in[15];
    const float* fc2b   = (const float*)d_in[16];

    cudaFuncSetAttribute(prep_kernel,
                         cudaFuncAttributeMaxDynamicSharedMemorySize,
                         (int)sizeof(PrepSM));
    cudaFuncSetAttribute(lstm_kernel,
                         cudaFuncAttributeMaxDynamicSharedMemorySize,
                         (int)sizeof(LSM));

    prep_kernel<<<4 * 66, 256, sizeof(PrepSM)>>>(
        x, lwx_W1, lwx_b1, lwx_W2, lwx_b2,
           lwh_W1, lwh_b1, lwh_W2, lwh_b2,
           lb_W1,  lb_b1,  lb_W2,  lb_b2);

    dim3 grid(NBLK, B_);
    lstm_kernel<<<grid, 256, sizeof(LSM)>>>(x, fc1W, fc1b, fc2W, fc2b,
                                            (float*)d_out);
}

// round 16
// speedup vs baseline: 2.5594x; 1.0745x over previous
#include <cuda_runtime.h>
#include <cuda_bf16.h>
#include <cstdint>

// ---------------- problem constants ----------------
constexpr int B_   = 64;
constexpr int T_   = 12;
constexpr int N_   = 325;
constexpr int E_   = 32;
constexpr int LH_  = 128;
constexpr int OUT_ = 12;
constexpr int C_   = 97;
constexpr int MOFF = 65;

constexpr int KP   = 152;   // 144 data + 8 pad; 304B rows (16B-aligned, conflict-free ldmatrix)
constexpr int MT   = 64;    // rows per CTA
constexpr int NBLK = (N_ + MT - 1) / MT;   // 6 -> grid 384

// ---------------- scratch ----------------
__device__ float g_hid[3 * 4 * B_ * LH_];   // stage-1 activations
// B operand per batch: [n=256][k=KP] bf16.  k: 0..63 Whi, 64..127 Wlo,
// 128=wxh 129=wxh 130=wxl 131=bh 132=bl 133.. zero
__device__ __align__(16) unsigned char g_B[B_][256 * KP * 2];

// ---------------- helpers ----------------
__device__ __forceinline__ float ex2a(float x) {
    float r; asm("ex2.approx.f32 %0, %1;" : "=f"(r) : "f"(x)); return r;
}
__device__ __forceinline__ float rcpa(float x) {
    float r; asm("rcp.approx.f32 %0, %1;" : "=f"(r) : "f"(x)); return r;
}
__device__ __forceinline__ float sig_a(float x) {
    return rcpa(1.0f + ex2a(-1.4426950408889634f * x));
}
__device__ __forceinline__ float tanh_a(float x) {
    float e = ex2a(2.8853900817779268f * x);
    return fmaf(-2.0f, rcpa(e + 1.0f), 1.0f);
}
__device__ __forceinline__ void mma_bf16(float& d0, float& d1, float& d2, float& d3,
                                         uint32_t a0, uint32_t a1, uint32_t a2, uint32_t a3,
                                         uint32_t b0, uint32_t b1) {
    asm volatile("mma.sync.aligned.m16n8k16.row.col.f32.bf16.bf16.f32 "
                 "{%0,%1,%2,%3},{%4,%5,%6,%7},{%8,%9},{%0,%1,%2,%3};"
                 : "+f"(d0), "+f"(d1), "+f"(d2), "+f"(d3)
                 : "r"(a0), "r"(a1), "r"(a2), "r"(a3), "r"(b0), "r"(b1));
}
__device__ __forceinline__ void ldm4(uint32_t& r0, uint32_t& r1,
                                     uint32_t& r2, uint32_t& r3, uint32_t a) {
    asm volatile("ldmatrix.sync.aligned.m8n8.x4.shared.b16 {%0,%1,%2,%3}, [%4];"
                 : "=r"(r0), "=r"(r1), "=r"(r2), "=r"(r3) : "r"(a));
}
__device__ __forceinline__ uint32_t smem_u32(const void* p) {
    uint32_t a;
    asm("{ .reg .u64 t; cvta.to.shared.u64 t, %1; cvt.u32.u64 %0, t; }" : "=r"(a) : "l"(p));
    return a;
}
__device__ __forceinline__ uint32_t packbf(float a, float b) {
    __nv_bfloat16 ha = __float2bfloat16(a), hb = __float2bfloat16(b);
    return (uint32_t)__bfloat16_as_ushort(ha) |
           ((uint32_t)__bfloat16_as_ushort(hb) << 16);
}

// ============ stage 1: meta + first MLP layer (R2 version, 12.6us) ============
__global__ void stage1_kernel(const float* __restrict__ x,
                              const float* __restrict__ wxW1, const float* __restrict__ wxB1,
                              const float* __restrict__ whW1, const float* __restrict__ whB1,
                              const float* __restrict__ lbW1, const float* __restrict__ lbB1) {
    int m = blockIdx.x >> 6, b = blockIdx.x & 63;
    const float* W1 = (m == 0) ? wxW1 : (m == 1) ? whW1 : lbW1;
    const float* b1 = (m == 0) ? wxB1 : (m == 1) ? whB1 : lbB1;
    __shared__ float meta[E_];
    int tid = threadIdx.x;
    if (tid < E_) {
        float s = 0.f;
#pragma unroll
        for (int t = 0; t < T_; t++)
            s += x[(size_t)((b * T_ + t) * N_) * C_ + MOFF + tid];
        meta[tid] = s * (1.0f / 12.0f);
    }
    __syncthreads();
#pragma unroll
    for (int g = 0; g < 4; g++) {
        float acc = b1[g * LH_ + tid];
#pragma unroll
        for (int e = 0; e < E_; e++)
            acc = fmaf(meta[e], W1[(g * E_ + e) * LH_ + tid], acc);
        g_hid[((m * 4 + g) * B_ + b) * LH_ + tid] = fmaxf(acc, 0.f);
    }
}

// ============ stage 2: second MLP layer -> packed g_B ============
__global__ void stage2_kernel(const float* __restrict__ wxW2, const float* __restrict__ wxB2,
                              const float* __restrict__ whW2, const float* __restrict__ whB2,
                              const float* __restrict__ lbW2, const float* __restrict__ lbB2) {
    __shared__ float hs[B_ * LH_];    // 32KB
    __shared__ float w2[LH_ * 64];    // 32KB
    int g  = blockIdx.x / 66;
    int tl = blockIdx.x % 66;
    int m  = (tl < 64) ? 1 : (tl == 64 ? 0 : 2);
    int tile = (m == 1) ? tl : 0;
    int tid = threadIdx.x;
    int o = tid & 63, bg = tid >> 6;

    const float* hsrc = g_hid + (m * 4 + g) * (B_ * LH_);
    for (int i = tid; i < B_ * LH_; i += 256) hs[i] = hsrc[i];
    const float* W2; const float* b2; int ostride;
    if (m == 1)      { W2 = whW2 + g * LH_ * 4096 + tile * 64; b2 = whB2 + g * 4096 + tile * 64; ostride = 4096; }
    else if (m == 0) { W2 = wxW2 + g * LH_ * 64;               b2 = wxB2 + g * 64;               ostride = 64; }
    else             { W2 = lbW2 + g * LH_ * 64;               b2 = lbB2 + g * 64;               ostride = 64; }
    for (int i = tid; i < LH_ * 64; i += 256) {
        int k = i >> 6, oo = i & 63;
        w2[i] = W2[k * ostride + oo];
    }
    __syncthreads();

    float bv = b2[o];
    float acc[16];
#pragma unroll
    for (int i = 0; i < 16; i++) acc[i] = bv;
    const float* hb = hs + bg * 16 * LH_;
#pragma unroll 4
    for (int k = 0; k < LH_; k++) {
        float w = w2[k * 64 + o];
#pragma unroll
        for (int i = 0; i < 16; i++)
            acc[i] = fmaf(hb[i * LH_ + k], w, acc[i]);
    }

    int nrow = g * 64 + o;
#pragma unroll
    for (int i = 0; i < 16; i++) {
        int b = bg * 16 + i;
        float v = acc[i];
        __nv_bfloat16 hi = __float2bfloat16(v);
        __nv_bfloat16 lo = __float2bfloat16(v - __bfloat162float(hi));
        __nv_bfloat16* dst = (__nv_bfloat16*)g_B[b] + nrow * KP;
        if (m == 1) {
            dst[tile]      = hi;
            dst[64 + tile] = lo;
        } else if (m == 0) {
            dst[128] = hi;
            dst[129] = hi;
            dst[130] = lo;
        } else {
            dst[131] = hi;
            dst[132] = lo;
        }
    }
    // k = 133..151 stay zero (device globals are zero-initialized; never read anyway)
}

// ============ LSTM via mma.sync: scheduled stream + B prefetch ============
struct LSM {
    union {
        __nv_bfloat16 Bs[256 * KP];   // 77824 B (used through the last mma)
        float P[64 * 64];             // 16384 B (final h; written only after last B read)
    };
    __nv_bfloat16 As[MT * KP];        // 19456 B
    float xs[MT * T_];                // 3072 B
};
// total 100352 B -> 2 CTAs/SM

__global__ void __launch_bounds__(256, 2)
lstm_kernel(const float* __restrict__ x,
            const float* __restrict__ fc1W, const float* __restrict__ fc1b,
            const float* __restrict__ fc2W, const float* __restrict__ fc2b,
            float* __restrict__ out) {
    extern __shared__ __align__(16) char smraw[];
    LSM* s = (LSM*)smraw;
    int b   = blockIdx.y;
    int n0  = blockIdx.x * MT;
    int tid = threadIdx.x;
    int w = tid >> 5, lane = tid & 31;
    int wm = w & 3, wn = w >> 2;
    int tq = lane >> 2, tr = lane & 3;

    // ---- stage B, zero A, stage x ----
    {
        const uint4* gb = (const uint4*)g_B[b];
        uint4* sb = (uint4*)s->Bs;
        for (int i = tid; i < 256 * KP * 2 / 16; i += 256) sb[i] = gb[i];
        uint4 z4 = make_uint4(0, 0, 0, 0);
        uint4* sa = (uint4*)s->As;
        for (int i = tid; i < MT * KP * 2 / 16; i += 256) sa[i] = z4;
        for (int i = tid; i < MT * T_; i += 256) {
            int m = i / T_, t = i - m * T_;
            int n = n0 + m;
            s->xs[i] = (n < N_) ? x[(size_t)((b * T_ + t) * N_ + n) * C_] : 0.f;
        }
    }
    __syncthreads();
    if (tid < MT) {   // const cols + x(t=0)
        __nv_bfloat16 one = __float2bfloat16(1.0f);
        __nv_bfloat16* ar = s->As + tid * KP;
        ar[131] = one; ar[132] = one;
        float xv = s->xs[tid * T_];
        __nv_bfloat16 xh = __float2bfloat16(xv);
        __nv_bfloat16 xl = __float2bfloat16(xv - __bfloat162float(xh));
        ar[128] = xh; ar[129] = xl; ar[130] = xh;
    }

    // ldmatrix per-lane addresses
    int arow  = (lane & 7) + (lane & 8);
    int akofs = (lane >= 16) ? 8 : 0;
    int brow  = (lane & 7) + ((lane >> 4) << 3);
    int bkofs = (lane & 8);
    uint32_t sA = smem_u32(s->As) + (uint32_t)(((wm * 16 + arow) * KP + akofs) * 2);
    uint32_t sB = smem_u32(s->Bs) + (uint32_t)(((wn * 32 + brow) * KP + bkofs) * 2);

    float cst[16];
#pragma unroll
    for (int i = 0; i < 16; i++) cst[i] = 0.f;

    int m1 = wm * 16 + tq, m2 = m1 + 8;

    for (int t = 0; t < T_; t++) {
        __syncthreads();   // A (h_{t-1}, x_t) ready

        float d0[16], d1[16], d2[16], d3[16];
#pragma unroll
        for (int nt = 0; nt < 16; nt++) { d0[nt] = d1[nt] = d2[nt] = d3[nt] = 0.f; }

#pragma unroll
        for (int cc = 0; cc < 4; cc++) {
            uint32_t h0, h1, h2, h3, l0, l1, l2, l3;
            ldm4(h0, h1, h2, h3, sA + cc * 32);        // hh frags
            ldm4(l0, l1, l2, l3, sA + 128 + cc * 32);  // hl frags
            // prefetch Bhi for block 0
            uint32_t bh0, bh1, bh2, bh3;
            ldm4(bh0, bh1, bh2, bh3, sB + cc * 32);
#pragma unroll
            for (int blk = 0; blk < 8; blk++) {
                int g = blk >> 1, p = blk & 1;
                uint32_t bofs = (uint32_t)((g * 64 + p * 16) * KP * 2);
                int n1 = g * 4 + 2 * p, n2 = n1 + 1;
                // Blo for this block (used 4 mmas later)
                uint32_t bl0, bl1, bl2, bl3;
                ldm4(bl0, bl1, bl2, bl3, sB + bofs + 128 + cc * 32);
                // prefetch Bhi for next block (used 6+ mmas later)
                uint32_t nh0 = 0, nh1 = 0, nh2 = 0, nh3 = 0;
                if (blk < 7) {
                    int gn = (blk + 1) >> 1, pn = (blk + 1) & 1;
                    uint32_t bofn = (uint32_t)((gn * 64 + pn * 16) * KP * 2);
                    ldm4(nh0, nh1, nh2, nh3, sB + bofn + cc * 32);
                }
                // scheduled mma stream: same-d distance 2
                mma_bf16(d0[n1], d1[n1], d2[n1], d3[n1], h0, h1, h2, h3, bh0, bh1);
                mma_bf16(d0[n2], d1[n2], d2[n2], d3[n2], h0, h1, h2, h3, bh2, bh3);
                mma_bf16(d0[n1], d1[n1], d2[n1], d3[n1], l0, l1, l2, l3, bh0, bh1);
                mma_bf16(d0[n2], d1[n2], d2[n2], d3[n2], l0, l1, l2, l3, bh2, bh3);
                mma_bf16(d0[n1], d1[n1], d2[n1], d3[n1], h0, h1, h2, h3, bl0, bl1);
                mma_bf16(d0[n2], d1[n2], d2[n2], d3[n2], h0, h1, h2, h3, bl2, bl3);
                bh0 = nh0; bh1 = nh1; bh2 = nh2; bh3 = nh3;
            }
        }
        // x-block (kA = kB = 128..143)
        {
            uint32_t a0, a1, a2, a3;
            ldm4(a0, a1, a2, a3, sA + 256);
#pragma unroll
            for (int g = 0; g < 4; g++)
#pragma unroll
                for (int p = 0; p < 2; p++) {
                    uint32_t bofs = (uint32_t)((g * 64 + p * 16) * KP * 2);
                    uint32_t b0, b1, b2, b3;
                    int n1 = g * 4 + 2 * p, n2 = n1 + 1;
                    ldm4(b0, b1, b2, b3, sB + bofs + 256);
                    mma_bf16(d0[n1], d1[n1], d2[n1], d3[n1], a0, a1, a2, a3, b0, b1);
                    mma_bf16(d0[n2], d1[n2], d2[n2], d3[n2], a0, a1, a2, a3, b2, b3);
                }
        }
        __syncthreads();   // all A/B reads done; safe to overwrite A (and P at t=T-1)

        // ---- warp-local epilogue ----
        if (wn == 0 && lane < 16 && t < T_ - 1) {   // x(t+1)
            int m = wm * 16 + lane;
            float xv = s->xs[m * T_ + t + 1];
            __nv_bfloat16 xh = __float2bfloat16(xv);
            __nv_bfloat16 xl = __float2bfloat16(xv - __bfloat162float(xh));
            __nv_bfloat16* ar = s->As + m * KP;
            ar[128] = xh; ar[129] = xl; ar[130] = xh;
        }
#pragma unroll
        for (int ntj = 0; ntj < 4; ntj++) {
            int jp = wn * 32 + ntj * 8 + 2 * tr;
            float G, I, F, O, cn;
            G = tanh_a(d0[ntj]);      I = sig_a(d0[4 + ntj]);
            F = sig_a(d0[8 + ntj]);   O = sig_a(d0[12 + ntj]);
            cn = fmaf(cst[ntj * 4 + 0], F, G * I); cst[ntj * 4 + 0] = cn;
            float h00 = tanh_a(cn) * O;
            G = tanh_a(d1[ntj]);      I = sig_a(d1[4 + ntj]);
            F = sig_a(d1[8 + ntj]);   O = sig_a(d1[12 + ntj]);
            cn = fmaf(cst[ntj * 4 + 1], F, G * I); cst[ntj * 4 + 1] = cn;
            float h01 = tanh_a(cn) * O;
            G = tanh_a(d2[ntj]);      I = sig_a(d2[4 + ntj]);
            F = sig_a(d2[8 + ntj]);   O = sig_a(d2[12 + ntj]);
            cn = fmaf(cst[ntj * 4 + 2], F, G * I); cst[ntj * 4 + 2] = cn;
            float h10 = tanh_a(cn) * O;
            G = tanh_a(d3[ntj]);      I = sig_a(d3[4 + ntj]);
            F = sig_a(d3[8 + ntj]);   O = sig_a(d3[12 + ntj]);
            cn = fmaf(cst[ntj * 4 + 3], F, G * I); cst[ntj * 4 + 3] = cn;
            float h11 = tanh_a(cn) * O;

            if (t < T_ - 1) {
                __nv_bfloat16 b00 = __float2bfloat16(h00);
                __nv_bfloat16 b01 = __float2bfloat16(h01);
                __nv_bfloat16 b10 = __float2bfloat16(h10);
                __nv_bfloat16 b11 = __float2bfloat16(h11);
                uint32_t hi0 = (uint32_t)__bfloat16_as_ushort(b00) |
                               ((uint32_t)__bfloat16_as_ushort(b01) << 16);
                uint32_t hi1 = (uint32_t)__bfloat16_as_ushort(b10) |
                               ((uint32_t)__bfloat16_as_ushort(b11) << 16);
                uint32_t lo0 = packbf(h00 - __bfloat162float(b00),
                                      h01 - __bfloat162float(b01));
                uint32_t lo1 = packbf(h10 - __bfloat162float(b10),
                                      h11 - __bfloat162float(b11));
                *(uint32_t*)(s->As + m1 * KP + jp)      = hi0;
                *(uint32_t*)(s->As + m1 * KP + 64 + jp) = lo0;
                *(uint32_t*)(s->As + m2 * KP + jp)      = hi1;
                *(uint32_t*)(s->As + m2 * KP + 64 + jp) = lo1;
            } else {
                s->P[jp * 64 + m1]       = h00;
                s->P[(jp + 1) * 64 + m1] = h01;
                s->P[jp * 64 + m2]       = h10;
                s->P[(jp + 1) * 64 + m2] = h11;
            }
        }
    }
    __syncthreads();   // final h visible

    // ---- output head: relu(h) @ fc1 -> relu -> @ fc2 ----
#pragma unroll
    for (int q = 0; q < 8; q++) {
        int row = w * 8 + q;
        int n = n0 + row;
        float acc = fc1b[lane];
#pragma unroll 16
        for (int i = 0; i < 64; i++) {
            float hv = fmaxf(s->P[i * 64 + row], 0.f);
            acc = fmaf(hv, fc1W[i * 32 + lane], acc);
        }
        float o1 = fmaxf(acc, 0.f);
        float acc2 = (lane < OUT_) ? fc2b[lane] : 0.f;
#pragma unroll
        for (int jj = 0; jj < 32; jj++) {
            float v  = __shfl_sync(0xffffffffu, o1, jj);
            float wv = (lane < OUT_) ? fc2W[jj * OUT_ + lane] : 0.f;
            acc2 = fmaf(v, wv, acc2);
        }
        if (lane < OUT_ && n < N_)
            out[(size_t)(b * OUT_ + lane) * N_ + n] = acc2;
    }
}

// ---------------- launcher ----------------
extern "C" void kernel_launch(void* const* d_in, const int* in_sizes, int n_in,
                              void* d_out, int out_size) {
    const float* x      = (const float*)d_in[0];
    const float* lwx_W1 = (const float*)d_in[1];
    const float* lwx_b1 = (const float*)d_in[2];
    const float* lwx_W2 = (const float*)d_in[3];
    const float* lwx_b2 = (const float*)d_in[4];
    const float* lwh_W1 = (const float*)d_in[5];
    const float* lwh_b1 = (const float*)d_in[6];
    const float* lwh_W2 = (const float*)d_in[7];
    const float* lwh_b2 = (const float*)d_in[8];
    const float* lb_W1  = (const float*)d_in[9];
    const float* lb_b1  = (const float*)d_in[10];
    const float* lb_W2  = (const float*)d_in[11];
    const float* lb_b2  = (const float*)d_in[12];
    const float* fc1W   = (const float*)d_in[13];
    const float* fc1b   = (const float*)d_in[14];
    const float* fc2W   = (const float*)d_in[15];
    const float* fc2b   = (const float*)d_in[16];

    cudaFuncSetAttribute(lstm_kernel,
                         cudaFuncAttributeMaxDynamicSharedMemorySize,
                         (int)sizeof(LSM));

    stage1_kernel<<<3 * B_, LH_>>>(x, lwx_W1, lwx_b1, lwh_W1, lwh_b1, lb_W1, lb_b1);
    stage2_kernel<<<4 * 66, 256>>>(lwx_W2, lwx_b2, lwh_W2, lwh_b2, lb_W2, lb_b2);

    dim3 grid(NBLK, B_);
    lstm_kernel<<<grid, 256, sizeof(LSM)>>>(x, fc1W, fc1b, fc2W, fc2b,
                                            (float*)d_out);
}

// round 17
// speedup vs baseline: 2.5828x; 1.0092x over previous
#include <cuda_runtime.h>
#include <cuda_bf16.h>
#include <cstdint>

// ---------------- problem constants ----------------
constexpr int B_   = 64;
constexpr int T_   = 12;
constexpr int N_   = 325;
constexpr int E_   = 32;
constexpr int LH_  = 128;
constexpr int OUT_ = 12;
constexpr int C_   = 97;
constexpr int MOFF = 65;

constexpr int KP   = 152;   // 144 data + 8 pad; 304B rows (16B-aligned, conflict-free ldmatrix)
constexpr int MT   = 64;    // rows per CTA
constexpr int NBLK = (N_ + MT - 1) / MT;   // 6 -> grid 384

// ---------------- scratch ----------------
__device__ float g_hid[3 * 4 * B_ * LH_];   // stage-1 activations
// B operand per batch: [n=256][k=KP] bf16.  k: 0..63 Whi, 64..127 Wlo,
// 128=wxh 129=wxh 130=wxl 131=bh 132=bl 133.. zero
__device__ __align__(16) unsigned char g_B[B_][256 * KP * 2];

// ---------------- helpers ----------------
__device__ __forceinline__ float ex2a(float x) {
    float r; asm("ex2.approx.f32 %0, %1;" : "=f"(r) : "f"(x)); return r;
}
__device__ __forceinline__ float rcpa(float x) {
    float r; asm("rcp.approx.f32 %0, %1;" : "=f"(r) : "f"(x)); return r;
}
__device__ __forceinline__ float sig_a(float x) {
    return rcpa(1.0f + ex2a(-1.4426950408889634f * x));
}
__device__ __forceinline__ float tanh_a(float x) {
    float e = ex2a(2.8853900817779268f * x);
    return fmaf(-2.0f, rcpa(e + 1.0f), 1.0f);
}
__device__ __forceinline__ void mma_bf16(float& d0, float& d1, float& d2, float& d3,
                                         uint32_t a0, uint32_t a1, uint32_t a2, uint32_t a3,
                                         uint32_t b0, uint32_t b1) {
    asm volatile("mma.sync.aligned.m16n8k16.row.col.f32.bf16.bf16.f32 "
                 "{%0,%1,%2,%3},{%4,%5,%6,%7},{%8,%9},{%0,%1,%2,%3};"
                 : "+f"(d0), "+f"(d1), "+f"(d2), "+f"(d3)
                 : "r"(a0), "r"(a1), "r"(a2), "r"(a3), "r"(b0), "r"(b1));
}
__device__ __forceinline__ void ldm4(uint32_t& r0, uint32_t& r1,
                                     uint32_t& r2, uint32_t& r3, uint32_t a) {
    asm volatile("ldmatrix.sync.aligned.m8n8.x4.shared.b16 {%0,%1,%2,%3}, [%4];"
                 : "=r"(r0), "=r"(r1), "=r"(r2), "=r"(r3) : "r"(a));
}
__device__ __forceinline__ uint32_t smem_u32(const void* p) {
    uint32_t a;
    asm("{ .reg .u64 t; cvta.to.shared.u64 t, %1; cvt.u32.u64 %0, t; }" : "=r"(a) : "l"(p));
    return a;
}
__device__ __forceinline__ uint32_t packbf(float a, float b) {
    __nv_bfloat16 ha = __float2bfloat16(a), hb = __float2bfloat16(b);
    return (uint32_t)__bfloat16_as_ushort(ha) |
           ((uint32_t)__bfloat16_as_ushort(hb) << 16);
}
// group-local barrier: 2 warps (64 threads) of one m-tile group
#define BARG(id) asm volatile("bar.sync %0, 64;" :: "r"(id) : "memory")

// ============ stage 1: meta + first MLP layer ============
__global__ void stage1_kernel(const float* __restrict__ x,
                              const float* __restrict__ wxW1, const float* __restrict__ wxB1,
                              const float* __restrict__ whW1, const float* __restrict__ whB1,
                              const float* __restrict__ lbW1, const float* __restrict__ lbB1) {
    int m = blockIdx.x >> 6, b = blockIdx.x & 63;
    const float* W1 = (m == 0) ? wxW1 : (m == 1) ? whW1 : lbW1;
    const float* b1 = (m == 0) ? wxB1 : (m == 1) ? whB1 : lbB1;
    __shared__ float meta[E_];
    int tid = threadIdx.x;
    if (tid < E_) {
        float s = 0.f;
#pragma unroll
        for (int t = 0; t < T_; t++)
            s += x[(size_t)((b * T_ + t) * N_) * C_ + MOFF + tid];
        meta[tid] = s * (1.0f / 12.0f);
    }
    __syncthreads();
#pragma unroll
    for (int g = 0; g < 4; g++) {
        float acc = b1[g * LH_ + tid];
#pragma unroll
        for (int e = 0; e < E_; e++)
            acc = fmaf(meta[e], W1[(g * E_ + e) * LH_ + tid], acc);
        g_hid[((m * 4 + g) * B_ + b) * LH_ + tid] = fmaxf(acc, 0.f);
    }
}

// ============ stage 2: second MLP layer -> packed g_B ============
__global__ void stage2_kernel(const float* __restrict__ wxW2, const float* __restrict__ wxB2,
                              const float* __restrict__ whW2, const float* __restrict__ whB2,
                              const float* __restrict__ lbW2, const float* __restrict__ lbB2) {
    __shared__ float hs[B_ * LH_];
    __shared__ float w2[LH_ * 64];
    int g  = blockIdx.x / 66;
    int tl = blockIdx.x % 66;
    int m  = (tl < 64) ? 1 : (tl == 64 ? 0 : 2);
    int tile = (m == 1) ? tl : 0;
    int tid = threadIdx.x;
    int o = tid & 63, bg = tid >> 6;

    const float* hsrc = g_hid + (m * 4 + g) * (B_ * LH_);
    for (int i = tid; i < B_ * LH_; i += 256) hs[i] = hsrc[i];
    const float* W2; const float* b2; int ostride;
    if (m == 1)      { W2 = whW2 + g * LH_ * 4096 + tile * 64; b2 = whB2 + g * 4096 + tile * 64; ostride = 4096; }
    else if (m == 0) { W2 = wxW2 + g * LH_ * 64;               b2 = wxB2 + g * 64;               ostride = 64; }
    else             { W2 = lbW2 + g * LH_ * 64;               b2 = lbB2 + g * 64;               ostride = 64; }
    for (int i = tid; i < LH_ * 64; i += 256) {
        int k = i >> 6, oo = i & 63;
        w2[i] = W2[k * ostride + oo];
    }
    __syncthreads();

    float bv = b2[o];
    float acc[16];
#pragma unroll
    for (int i = 0; i < 16; i++) acc[i] = bv;
    const float* hb = hs + bg * 16 * LH_;
#pragma unroll 4
    for (int k = 0; k < LH_; k++) {
        float w = w2[k * 64 + o];
#pragma unroll
        for (int i = 0; i < 16; i++)
            acc[i] = fmaf(hb[i * LH_ + k], w, acc[i]);
    }

    int nrow = g * 64 + o;
#pragma unroll
    for (int i = 0; i < 16; i++) {
        int b = bg * 16 + i;
        float v = acc[i];
        __nv_bfloat16 hi = __float2bfloat16(v);
        __nv_bfloat16 lo = __float2bfloat16(v - __bfloat162float(hi));
        __nv_bfloat16* dst = (__nv_bfloat16*)g_B[b] + nrow * KP;
        if (m == 1) {
            dst[tile]      = hi;
            dst[64 + tile] = lo;
        } else if (m == 0) {
            dst[128] = hi;
            dst[129] = hi;
            dst[130] = lo;
        } else {
            dst[131] = hi;
            dst[132] = lo;
        }
    }
}

// ============ LSTM via mma.sync: group-decoupled timeline ============
struct LSM {
    union {
        __nv_bfloat16 Bs[256 * KP];   // 77824 B (used through the last mma)
        float P[64 * 64];             // 16384 B (final h; written after post-loop full sync)
    };
    __nv_bfloat16 As[MT * KP];        // 19456 B
    float xs[MT * T_];                // 3072 B
};
// total 100352 B -> 2 CTAs/SM

__global__ void __launch_bounds__(256, 2)
lstm_kernel(const float* __restrict__ x,
            const float* __restrict__ fc1W, const float* __restrict__ fc1b,
            const float* __restrict__ fc2W, const float* __restrict__ fc2b,
            float* __restrict__ out) {
    extern __shared__ __align__(16) char smraw[];
    LSM* s = (LSM*)smraw;
    int b   = blockIdx.y;
    int n0  = blockIdx.x * MT;
    int tid = threadIdx.x;
    int w = tid >> 5, lane = tid & 31;
    int wm = w & 3, wn = w >> 2;          // group = wm (2 warps); independent across groups
    int tq = lane >> 2, tr = lane & 3;
    int barid = 1 + wm;

    // ---- stage B, zero A, stage x ----
    {
        const uint4* gb = (const uint4*)g_B[b];
        uint4* sb = (uint4*)s->Bs;
        for (int i = tid; i < 256 * KP * 2 / 16; i += 256) sb[i] = gb[i];
        uint4 z4 = make_uint4(0, 0, 0, 0);
        uint4* sa = (uint4*)s->As;
        for (int i = tid; i < MT * KP * 2 / 16; i += 256) sa[i] = z4;
        for (int i = tid; i < MT * T_; i += 256) {
            int m = i / T_, t = i - m * T_;
            int n = n0 + m;
            s->xs[i] = (n < N_) ? x[(size_t)((b * T_ + t) * N_ + n) * C_] : 0.f;
        }
    }
    __syncthreads();
    if (tid < MT) {   // const cols + x(t=0)
        __nv_bfloat16 one = __float2bfloat16(1.0f);
        __nv_bfloat16* ar = s->As + tid * KP;
        ar[131] = one; ar[132] = one;
        float xv = s->xs[tid * T_];
        __nv_bfloat16 xh = __float2bfloat16(xv);
        __nv_bfloat16 xl = __float2bfloat16(xv - __bfloat162float(xh));
        ar[128] = xh; ar[129] = xl; ar[130] = xh;
    }
    __syncthreads();   // all init visible to all groups

    // ldmatrix per-lane addresses
    int arow  = (lane & 7) + (lane & 8);
    int akofs = (lane >= 16) ? 8 : 0;
    int brow  = (lane & 7) + ((lane >> 4) << 3);
    int bkofs = (lane & 8);
    uint32_t sA = smem_u32(s->As) + (uint32_t)(((wm * 16 + arow) * KP + akofs) * 2);
    uint32_t sB = smem_u32(s->Bs) + (uint32_t)(((wn * 32 + brow) * KP + bkofs) * 2);

    float cst[16];
#pragma unroll
    for (int i = 0; i < 16; i++) cst[i] = 0.f;

    int m1 = wm * 16 + tq, m2 = m1 + 8;
    float hfin[16];

    for (int t = 0; t < T_; t++) {
        BARG(barid);   // group's A (h_{t-1}, x_t) ready

        float d0[16], d1[16], d2[16], d3[16];
#pragma unroll
        for (int nt = 0; nt < 16; nt++) { d0[nt] = d1[nt] = d2[nt] = d3[nt] = 0.f; }

#pragma unroll
        for (int cc = 0; cc < 4; cc++) {
            uint32_t h0, h1, h2, h3, l0, l1, l2, l3;
            ldm4(h0, h1, h2, h3, sA + cc * 32);        // hh frags
            ldm4(l0, l1, l2, l3, sA + 128 + cc * 32);  // hl frags
            uint32_t bh0, bh1, bh2, bh3;
            ldm4(bh0, bh1, bh2, bh3, sB + cc * 32);
#pragma unroll
            for (int blk = 0; blk < 8; blk++) {
                int g = blk >> 1, p = blk & 1;
                uint32_t bofs = (uint32_t)((g * 64 + p * 16) * KP * 2);
                int n1 = g * 4 + 2 * p, n2 = n1 + 1;
                uint32_t bl0, bl1, bl2, bl3;
                ldm4(bl0, bl1, bl2, bl3, sB + bofs + 128 + cc * 32);
                uint32_t nh0 = 0, nh1 = 0, nh2 = 0, nh3 = 0;
                if (blk < 7) {
                    int gn = (blk + 1) >> 1, pn = (blk + 1) & 1;
                    uint32_t bofn = (uint32_t)((gn * 64 + pn * 16) * KP * 2);
                    ldm4(nh0, nh1, nh2, nh3, sB + bofn + cc * 32);
                }
                mma_bf16(d0[n1], d1[n1], d2[n1], d3[n1], h0, h1, h2, h3, bh0, bh1);
                mma_bf16(d0[n2], d1[n2], d2[n2], d3[n2], h0, h1, h2, h3, bh2, bh3);
                mma_bf16(d0[n1], d1[n1], d2[n1], d3[n1], l0, l1, l2, l3, bh0, bh1);
                mma_bf16(d0[n2], d1[n2], d2[n2], d3[n2], l0, l1, l2, l3, bh2, bh3);
                mma_bf16(d0[n1], d1[n1], d2[n1], d3[n1], h0, h1, h2, h3, bl0, bl1);
                mma_bf16(d0[n2], d1[n2], d2[n2], d3[n2], h0, h1, h2, h3, bl2, bl3);
                bh0 = nh0; bh1 = nh1; bh2 = nh2; bh3 = nh3;
            }
        }
        // x-block (kA = kB = 128..143)
        {
            uint32_t a0, a1, a2, a3;
            ldm4(a0, a1, a2, a3, sA + 256);
#pragma unroll
            for (int g = 0; g < 4; g++)
#pragma unroll
                for (int p = 0; p < 2; p++) {
                    uint32_t bofs = (uint32_t)((g * 64 + p * 16) * KP * 2);
                    uint32_t b0, b1, b2, b3;
                    int n1 = g * 4 + 2 * p, n2 = n1 + 1;
                    ldm4(b0, b1, b2, b3, sB + bofs + 256);
                    mma_bf16(d0[n1], d1[n1], d2[n1], d3[n1], a0, a1, a2, a3, b0, b1);
                    mma_bf16(d0[n2], d1[n2], d2[n2], d3[n2], a0, a1, a2, a3, b2, b3);
                }
        }
        BARG(barid);   // group's A reads done; safe to overwrite group's A rows

        // ---- group-local epilogue ----
        if (wn == 0 && lane < 16 && t < T_ - 1) {   // x(t+1) for this group's rows
            int m = wm * 16 + lane;
            float xv = s->xs[m * T_ + t + 1];
            __nv_bfloat16 xh = __float2bfloat16(xv);
            __nv_bfloat16 xl = __float2bfloat16(xv - __bfloat162float(xh));
            __nv_bfloat16* ar = s->As + m * KP;
            ar[128] = xh; ar[129] = xl; ar[130] = xh;
        }
#pragma unroll
        for (int ntj = 0; ntj < 4; ntj++) {
            int jp = wn * 32 + ntj * 8 + 2 * tr;
            float G, I, F, O, cn;
            G = tanh_a(d0[ntj]);      I = sig_a(d0[4 + ntj]);
            F = sig_a(d0[8 + ntj]);   O = sig_a(d0[12 + ntj]);
            cn = fmaf(cst[ntj * 4 + 0], F, G * I); cst[ntj * 4 + 0] = cn;
            float h00 = tanh_a(cn) * O;
            G = tanh_a(d1[ntj]);      I = sig_a(d1[4 + ntj]);
            F = sig_a(d1[8 + ntj]);   O = sig_a(d1[12 + ntj]);
            cn = fmaf(cst[ntj * 4 + 1], F, G * I); cst[ntj * 4 + 1] = cn;
            float h01 = tanh_a(cn) * O;
            G = tanh_a(d2[ntj]);      I = sig_a(d2[4 + ntj]);
            F = sig_a(d2[8 + ntj]);   O = sig_a(d2[12 + ntj]);
            cn = fmaf(cst[ntj * 4 + 2], F, G * I); cst[ntj * 4 + 2] = cn;
            float h10 = tanh_a(cn) * O;
            G = tanh_a(d3[ntj]);      I = sig_a(d3[4 + ntj]);
            F = sig_a(d3[8 + ntj]);   O = sig_a(d3[12 + ntj]);
            cn = fmaf(cst[ntj * 4 + 3], F, G * I); cst[ntj * 4 + 3] = cn;
            float h11 = tanh_a(cn) * O;

            if (t < T_ - 1) {
                __nv_bfloat16 b00 = __float2bfloat16(h00);
                __nv_bfloat16 b01 = __float2bfloat16(h01);
                __nv_bfloat16 b10 = __float2bfloat16(h10);
                __nv_bfloat16 b11 = __float2bfloat16(h11);
                uint32_t hi0 = (uint32_t)__bfloat16_as_ushort(b00) |
                               ((uint32_t)__bfloat16_as_ushort(b01) << 16);
                uint32_t hi1 = (uint32_t)__bfloat16_as_ushort(b10) |
                               ((uint32_t)__bfloat16_as_ushort(b11) << 16);
                uint32_t lo0 = packbf(h00 - __bfloat162float(b00),
                                      h01 - __bfloat162float(b01));
                uint32_t lo1 = packbf(h10 - __bfloat162float(b10),
                                      h11 - __bfloat162float(b11));
                *(uint32_t*)(s->As + m1 * KP + jp)      = hi0;
                *(uint32_t*)(s->As + m1 * KP + 64 + jp) = lo0;
                *(uint32_t*)(s->As + m2 * KP + jp)      = hi1;
                *(uint32_t*)(s->As + m2 * KP + 64 + jp) = lo1;
            } else {
                hfin[ntj * 4 + 0] = h00;
                hfin[ntj * 4 + 1] = h01;
                hfin[ntj * 4 + 2] = h10;
                hfin[ntj * 4 + 3] = h11;
            }
        }
    }

    __syncthreads();   // ALL groups past their last mma; Bs no longer needed
#pragma unroll
    for (int ntj = 0; ntj < 4; ntj++) {   // final h -> P (overlays Bs)
        int jp = wn * 32 + ntj * 8 + 2 * tr;
        s->P[jp * 64 + m1]       = hfin[ntj * 4 + 0];
        s->P[(jp + 1) * 64 + m1] = hfin[ntj * 4 + 1];
        s->P[jp * 64 + m2]       = hfin[ntj * 4 + 2];
        s->P[(jp + 1) * 64 + m2] = hfin[ntj * 4 + 3];
    }
    __syncthreads();   // final h visible

    // ---- output head: relu(h) @ fc1 -> relu -> @ fc2 ----
#pragma unroll
    for (int q = 0; q < 8; q++) {
        int row = w * 8 + q;
        int n = n0 + row;
        float acc = fc1b[lane];
#pragma unroll 16
        for (int i = 0; i < 64; i++) {
            float hv = fmaxf(s->P[i * 64 + row], 0.f);
            acc = fmaf(hv, fc1W[i * 32 + lane], acc);
        }
        float o1 = fmaxf(acc, 0.f);
        float acc2 = (lane < OUT_) ? fc2b[lane] : 0.f;
#pragma unroll
        for (int jj = 0; jj < 32; jj++) {
            float v  = __shfl_sync(0xffffffffu, o1, jj);
            float wv = (lane < OUT_) ? fc2W[jj * OUT_ + lane] : 0.f;
            acc2 = fmaf(v, wv, acc2);
        }
        if (lane < OUT_ && n < N_)
            out[(size_t)(b * OUT_ + lane) * N_ + n] = acc2;
    }
}

// ---------------- launcher ----------------
extern "C" void kernel_launch(void* const* d_in, const int* in_sizes, int n_in,
                              void* d_out, int out_size) {
    const float* x      = (const float*)d_in[0];
    const float* lwx_W1 = (const float*)d_in[1];
    const float* lwx_b1 = (const float*)d_in[2];
    const float* lwx_W2 = (const float*)d_in[3];
    const float* lwx_b2 = (const float*)d_in[4];
    const float* lwh_W1 = (const float*)d_in[5];
    const float* lwh_b1 = (const float*)d_in[6];
    const float* lwh_W2 = (const float*)d_in[7];
    const float* lwh_b2 = (const float*)d_in[8];
    const float* lb_W1  = (const float*)d_in[9];
    const float* lb_b1  = (const float*)d_in[10];
    const float* lb_W2  = (const float*)d_in[11];
    const float* lb_b2  = (const float*)d_in[12];
    const float* fc1W   = (const float*)d_in[13];
    const float* fc1b   = (const float*)d_in[14];
    const float* fc2W   = (const float*)d_in[15];
    const float* fc2b   = (const float*)d_in[16];

    cudaFuncSetAttribute(lstm_kernel,
                         cudaFuncAttributeMaxDynamicSharedMemorySize,
                         (int)sizeof(LSM));

    stage1_kernel<<<3 * B_, LH_>>>(x, lwx_W1, lwx_b1, lwh_W1, lwh_b1, lb_W1, lb_b1);
    stage2_kernel<<<4 * 66, 256>>>(lwx_W2, lwx_b2, lwh_W2, lwh_b2, lb_W2, lb_b2);

    dim3 grid(NBLK, B_);
    lstm_kernel<<<grid, 256, sizeof(LSM)>>>(x, fc1W, fc1b, fc2W, fc2b,
                                            (float*)d_out);
}